// round 2
// baseline (speedup 1.0000x reference)
#include <cuda_runtime.h>

#define N_TOK 4096
#define C_DIM 256
#define NH 8
#define HD 32
#define SCALE 0.17677669529663687f  // 1/sqrt(32)

// Scratch (device globals; no allocation allowed)
__device__ float g_keep[N_TOK];
__device__ float g_q[NH * N_TOK * HD];
__device__ float g_k[NH * N_TOK * HD];
__device__ float g_v[NH * N_TOK * HD];
__device__ float g_ao[N_TOK * C_DIM];

// ---------------------------------------------------------------------------
// Kernel 1: keep mask = 3x3 morphological dilation of (dbz >= 15), per frame.
// (valid | boundary == dilated, since valid => dilated)
// ---------------------------------------------------------------------------
__global__ void keep_kernel(const float* __restrict__ dbz) {
    int idx = blockIdx.x * blockDim.x + threadIdx.x;
    if (idx >= N_TOK) return;
    int t = idx >> 10;
    int h = (idx >> 5) & 31;
    int w = idx & 31;
    const float* f = dbz + t * 1024;
    bool any = false;
#pragma unroll
    for (int dh = -1; dh <= 1; dh++) {
        int hh = h + dh;
        if (hh < 0 || hh >= 32) continue;
#pragma unroll
        for (int dw = -1; dw <= 1; dw++) {
            int ww = w + dw;
            if (ww < 0 || ww >= 32) continue;
            any = any || (f[hh * 32 + ww] >= 15.0f);
        }
    }
    g_keep[idx] = any ? 1.0f : 0.0f;
}

// ---------------------------------------------------------------------------
// Kernel 2: QKV GEMM.  qkv[n][j] = sum_c x[n][c] * qkv_w[j][c]
// j = sel*256 + head*32 + d ; scatter into head-major g_q/g_k/g_v[h][n][d].
// 64x64 tile, 256 threads, 4x4 register blocking.
// ---------------------------------------------------------------------------
__global__ void __launch_bounds__(256) qkv_kernel(const float* __restrict__ x,
                                                  const float* __restrict__ w) {
    __shared__ float As[64][33];
    __shared__ float Bs[64][33];
    int tid = threadIdx.x;
    int tx = tid & 15, ty = tid >> 4;
    int row0 = blockIdx.y * 64;
    int col0 = blockIdx.x * 64;
    float acc[4][4] = {};
    for (int k0 = 0; k0 < 256; k0 += 32) {
#pragma unroll
        for (int i = 0; i < 8; i++) {
            int e = tid + i * 256;
            int r = e >> 5, c = e & 31;
            As[r][c] = x[(row0 + r) * 256 + k0 + c];
            Bs[r][c] = w[(col0 + r) * 256 + k0 + c];
        }
        __syncthreads();
#pragma unroll
        for (int kk = 0; kk < 32; kk++) {
            float a[4], b[4];
#pragma unroll
            for (int i = 0; i < 4; i++) a[i] = As[ty * 4 + i][kk];
#pragma unroll
            for (int j = 0; j < 4; j++) b[j] = Bs[tx * 4 + j][kk];
#pragma unroll
            for (int i = 0; i < 4; i++)
#pragma unroll
                for (int j = 0; j < 4; j++) acc[i][j] += a[i] * b[j];
        }
        __syncthreads();
    }
#pragma unroll
    for (int i = 0; i < 4; i++) {
        int n = row0 + ty * 4 + i;
#pragma unroll
        for (int j = 0; j < 4; j++) {
            int jj = col0 + tx * 4 + j;
            int sel = jj >> 8;
            int head = (jj >> 5) & 7;
            int d = jj & 31;
            float* dst = (sel == 0) ? g_q : (sel == 1) ? g_k : g_v;
            dst[(head * N_TOK + n) * HD + d] = acc[i][j];
        }
    }
}

// ---------------------------------------------------------------------------
// Kernel 3: flash-style masked attention, one (head, 64-query tile) per block.
// No running max (logits are O(1) for this data; clamp at 60 for safety).
// 128 threads: QK uses 16x8 thread grid (4x8 outputs), PV uses 16x8 (4q x 4d).
// ---------------------------------------------------------------------------
__global__ void __launch_bounds__(128) attn_kernel() {
    __shared__ float Qs[64][33];
    __shared__ float Ks[64][33];
    __shared__ float Vs[64][33];
    __shared__ float Ps[64][65];
    __shared__ float keeps[64];
    __shared__ float Lred[8][64];
    int tid = threadIdx.x;
    int head = blockIdx.y;
    int q0 = blockIdx.x * 64;
    const float* Qg = g_q + head * N_TOK * HD;
    const float* Kg = g_k + head * N_TOK * HD;
    const float* Vg = g_v + head * N_TOK * HD;

    // Load Q tile once, pre-scaled.
#pragma unroll
    for (int i = 0; i < 16; i++) {
        int e = tid + i * 128;
        int r = e >> 5, c = e & 31;
        Qs[r][c] = Qg[(q0 + r) * HD + c] * SCALE;
    }
    int tq = tid & 15;  // row group (shared by QK and PV phases)
    int tk = tid >> 4;  // col group (QK) / dim group (PV)

    float o[4][4] = {};
    float lpart[4] = {};

    for (int k0 = 0; k0 < N_TOK; k0 += 64) {
#pragma unroll
        for (int i = 0; i < 16; i++) {
            int e = tid + i * 128;
            int r = e >> 5, c = e & 31;
            Ks[r][c] = Kg[(k0 + r) * HD + c];
            Vs[r][c] = Vg[(k0 + r) * HD + c];
        }
        if (tid < 64) keeps[tid] = g_keep[k0 + tid];
        __syncthreads();

        // S = Qs @ Ks^T  (4x8 per thread)
        float s[4][8] = {};
#pragma unroll
        for (int d = 0; d < 32; d++) {
            float qa[4], kb[8];
#pragma unroll
            for (int i = 0; i < 4; i++) qa[i] = Qs[tq * 4 + i][d];
#pragma unroll
            for (int j = 0; j < 8; j++) kb[j] = Ks[tk * 8 + j][d];
#pragma unroll
            for (int i = 0; i < 4; i++)
#pragma unroll
                for (int j = 0; j < 8; j++) s[i][j] += qa[i] * kb[j];
        }
        // P = keep * exp(S); accumulate row sums; stage P for PV GEMM.
#pragma unroll
        for (int i = 0; i < 4; i++)
#pragma unroll
            for (int j = 0; j < 8; j++) {
                float p = keeps[tk * 8 + j] * __expf(fminf(s[i][j], 60.0f));
                lpart[i] += p;
                Ps[tq * 4 + i][tk * 8 + j] = p;
            }
        __syncthreads();

        // O += P @ V  (4q x 4d per thread)
#pragma unroll
        for (int kk = 0; kk < 64; kk++) {
            float pa[4], vb[4];
#pragma unroll
            for (int i = 0; i < 4; i++) pa[i] = Ps[tq * 4 + i][kk];
#pragma unroll
            for (int j = 0; j < 4; j++) vb[j] = Vs[kk][tk * 4 + j];
#pragma unroll
            for (int i = 0; i < 4; i++)
#pragma unroll
                for (int j = 0; j < 4; j++) o[i][j] += pa[i] * vb[j];
        }
        __syncthreads();
    }

    // Reduce row sums l across the 8 column-groups, normalize, write out.
#pragma unroll
    for (int i = 0; i < 4; i++) Lred[tk][tq * 4 + i] = lpart[i];
    __syncthreads();
#pragma unroll
    for (int i = 0; i < 4; i++) {
        int r = tq * 4 + i;
        float l = 0.0f;
#pragma unroll
        for (int g = 0; g < 8; g++) l += Lred[g][r];
        float inv = 1.0f / fmaxf(l, 1e-30f);
        int n = q0 + r;
#pragma unroll
        for (int j = 0; j < 4; j++)
            g_ao[n * C_DIM + head * HD + tk * 4 + j] = o[i][j] * inv;
    }
}

// ---------------------------------------------------------------------------
// Kernel 4: proj GEMM + bias, zero non-kept queries, add residual.
// out[n][c] = keep[n] * (sum_k ao[n][k]*proj_w[c][k] + b[c]) + x[n][c]
// ---------------------------------------------------------------------------
__global__ void __launch_bounds__(256) proj_kernel(const float* __restrict__ x,
                                                   const float* __restrict__ w,
                                                   const float* __restrict__ b,
                                                   float* __restrict__ out) {
    __shared__ float As[64][33];
    __shared__ float Bs[64][33];
    int tid = threadIdx.x;
    int tx = tid & 15, ty = tid >> 4;
    int row0 = blockIdx.y * 64;
    int col0 = blockIdx.x * 64;
    float acc[4][4] = {};
    for (int k0 = 0; k0 < 256; k0 += 32) {
#pragma unroll
        for (int i = 0; i < 8; i++) {
            int e = tid + i * 256;
            int r = e >> 5, c = e & 31;
            As[r][c] = g_ao[(row0 + r) * 256 + k0 + c];
            Bs[r][c] = w[(col0 + r) * 256 + k0 + c];
        }
        __syncthreads();
#pragma unroll
        for (int kk = 0; kk < 32; kk++) {
            float a[4], bb[4];
#pragma unroll
            for (int i = 0; i < 4; i++) a[i] = As[ty * 4 + i][kk];
#pragma unroll
            for (int j = 0; j < 4; j++) bb[j] = Bs[tx * 4 + j][kk];
#pragma unroll
            for (int i = 0; i < 4; i++)
#pragma unroll
                for (int j = 0; j < 4; j++) acc[i][j] += a[i] * bb[j];
        }
        __syncthreads();
    }
#pragma unroll
    for (int i = 0; i < 4; i++) {
        int n = row0 + ty * 4 + i;
        float kp = g_keep[n];
#pragma unroll
        for (int j = 0; j < 4; j++) {
            int cc = col0 + tx * 4 + j;
            out[n * 256 + cc] = kp * (acc[i][j] + b[cc]) + x[n * 256 + cc];
        }
    }
}

extern "C" void kernel_launch(void* const* d_in, const int* in_sizes, int n_in,
                              void* d_out, int out_size) {
    const float* x      = (const float*)d_in[0];
    const float* dbz    = (const float*)d_in[1];
    const float* qkv_w  = (const float*)d_in[2];
    const float* proj_w = (const float*)d_in[3];
    const float* proj_b = (const float*)d_in[4];
    float* out = (float*)d_out;

    keep_kernel<<<16, 256>>>(dbz);
    qkv_kernel<<<dim3(12, 64), 256>>>(x, qkv_w);
    attn_kernel<<<dim3(64, 8), 128>>>();
    proj_kernel<<<dim3(4, 64), 256>>>(x, proj_w, proj_b, out);
}

// round 4
// speedup vs baseline: 1.6340x; 1.6340x over previous
#include <cuda_runtime.h>

#define N_TOK 4096
#define C_DIM 256
#define NH 8
#define HD 32
#define SCALE 0.17677669529663687f  // 1/sqrt(32)

// Scratch (device globals; no allocation allowed)
__device__ float g_keep[N_TOK];
__device__ float g_q[NH * N_TOK * HD];
__device__ float g_k[NH * N_TOK * HD];
__device__ float g_v[NH * N_TOK * HD];
__device__ float g_ao[N_TOK * C_DIM];

// ---------------------------------------------------------------------------
// Helpers: tf32 conversion + m16n8k8 tf32 mma
// ---------------------------------------------------------------------------
__device__ __forceinline__ float tf32f(float f) {
    unsigned u;
    asm("cvt.rna.tf32.f32 %0, %1;" : "=r"(u) : "f"(f));
    return __uint_as_float(u);
}

__device__ __forceinline__ void mma8(float* c, const unsigned* a, unsigned b0, unsigned b1) {
    asm volatile(
        "mma.sync.aligned.m16n8k8.row.col.f32.tf32.tf32.f32 "
        "{%0,%1,%2,%3}, {%4,%5,%6,%7}, {%8,%9}, {%0,%1,%2,%3};"
        : "+f"(c[0]), "+f"(c[1]), "+f"(c[2]), "+f"(c[3])
        : "r"(a[0]), "r"(a[1]), "r"(a[2]), "r"(a[3]), "r"(b0), "r"(b1));
}

// ---------------------------------------------------------------------------
// Kernel 1: keep mask = 3x3 morphological dilation of (dbz >= 15), per frame.
// ---------------------------------------------------------------------------
__global__ void keep_kernel(const float* __restrict__ dbz) {
    int idx = blockIdx.x * blockDim.x + threadIdx.x;
    if (idx >= N_TOK) return;
    int t = idx >> 10;
    int h = (idx >> 5) & 31;
    int w = idx & 31;
    const float* f = dbz + t * 1024;
    bool any = false;
#pragma unroll
    for (int dh = -1; dh <= 1; dh++) {
        int hh = h + dh;
        if (hh < 0 || hh >= 32) continue;
#pragma unroll
        for (int dw = -1; dw <= 1; dw++) {
            int ww = w + dw;
            if (ww < 0 || ww >= 32) continue;
            any = any || (f[hh * 32 + ww] >= 15.0f);
        }
    }
    g_keep[idx] = any ? 1.0f : 0.0f;
}

// ---------------------------------------------------------------------------
// Kernel 2: QKV GEMM (SIMT fp32, unchanged this round).
// ---------------------------------------------------------------------------
__global__ void __launch_bounds__(256) qkv_kernel(const float* __restrict__ x,
                                                  const float* __restrict__ w) {
    __shared__ float As[64][33];
    __shared__ float Bs[64][33];
    int tid = threadIdx.x;
    int tx = tid & 15, ty = tid >> 4;
    int row0 = blockIdx.y * 64;
    int col0 = blockIdx.x * 64;
    float acc[4][4] = {};
    for (int k0 = 0; k0 < 256; k0 += 32) {
#pragma unroll
        for (int i = 0; i < 8; i++) {
            int e = tid + i * 256;
            int r = e >> 5, c = e & 31;
            As[r][c] = x[(row0 + r) * 256 + k0 + c];
            Bs[r][c] = w[(col0 + r) * 256 + k0 + c];
        }
        __syncthreads();
#pragma unroll
        for (int kk = 0; kk < 32; kk++) {
            float a[4], b[4];
#pragma unroll
            for (int i = 0; i < 4; i++) a[i] = As[ty * 4 + i][kk];
#pragma unroll
            for (int j = 0; j < 4; j++) b[j] = Bs[tx * 4 + j][kk];
#pragma unroll
            for (int i = 0; i < 4; i++)
#pragma unroll
                for (int j = 0; j < 4; j++) acc[i][j] += a[i] * b[j];
        }
        __syncthreads();
    }
#pragma unroll
    for (int i = 0; i < 4; i++) {
        int n = row0 + ty * 4 + i;
#pragma unroll
        for (int j = 0; j < 4; j++) {
            int jj = col0 + tx * 4 + j;
            int sel = jj >> 8;
            int head = (jj >> 5) & 7;
            int d = jj & 31;
            float* dst = (sel == 0) ? g_q : (sel == 1) ? g_k : g_v;
            dst[(head * N_TOK + n) * HD + d] = acc[i][j];
        }
    }
}

// ---------------------------------------------------------------------------
// Kernel 3: flash attention with tf32 mma.sync (m16n8k8).
// One (head, 64-query tile) per block, 128 threads = 4 warps.
// Warp w owns S/O rows [16w, 16w+16). No running max (logits O(1); clamp 60).
// Smem strides chosen so every fragment load is bank-conflict-free.
// ---------------------------------------------------------------------------
__global__ void __launch_bounds__(128) attn_kernel() {
    __shared__ float Qs[64][36];   // [q][d]   tf32 bits
    __shared__ float Ks[64][36];   // [key][d] tf32 bits
    __shared__ float Vs[64][40];   // [key][d] tf32 bits
    __shared__ float Ps[64][68];   // [q][key] tf32 bits
    __shared__ float keeps[64];

    int tid = threadIdx.x;
    int lane = tid & 31;
    int warp = tid >> 5;
    int gid = lane >> 2;   // 0..7
    int tig = lane & 3;    // 0..3
    int m0 = warp * 16;

    int head = blockIdx.y;
    int q0 = blockIdx.x * 64;
    const float* Qg = g_q + head * N_TOK * HD;
    const float* Kg = g_k + head * N_TOK * HD;
    const float* Vg = g_v + head * N_TOK * HD;

    // Load Q tile once: pre-scaled, tf32-rounded.
#pragma unroll
    for (int i = 0; i < 16; i++) {
        int e = tid + i * 128;
        int r = e >> 5, c = e & 31;
        Qs[r][c] = tf32f(Qg[(q0 + r) * HD + c] * SCALE);
    }
    __syncthreads();

    // A fragments for Q (fixed for whole kernel): aq[kstep][4]
    unsigned aq[4][4];
#pragma unroll
    for (int kk = 0; kk < 4; kk++) {
        int kc = kk * 8;
        aq[kk][0] = __float_as_uint(Qs[m0 + gid][kc + tig]);
        aq[kk][1] = __float_as_uint(Qs[m0 + 8 + gid][kc + tig]);
        aq[kk][2] = __float_as_uint(Qs[m0 + gid][kc + tig + 4]);
        aq[kk][3] = __float_as_uint(Qs[m0 + 8 + gid][kc + tig + 4]);
    }

    float oc[4][4] = {};   // O accumulators: 4 n-tiles of 8 dims
    float lp0 = 0.0f, lp1 = 0.0f;  // row sums for rows m0+gid, m0+8+gid

    for (int k0 = 0; k0 < N_TOK; k0 += 64) {
        // Load K/V tile (tf32-rounded) + keep flags.
#pragma unroll
        for (int i = 0; i < 16; i++) {
            int e = tid + i * 128;
            int r = e >> 5, c = e & 31;
            Ks[r][c] = tf32f(Kg[(k0 + r) * HD + c]);
            Vs[r][c] = tf32f(Vg[(k0 + r) * HD + c]);
        }
        if (tid < 64) keeps[tid] = g_keep[k0 + tid];
        __syncthreads();

        // ---- S = Qs @ Ks^T : 8 n-tiles x 4 k-steps per warp ----
        float sc[8][4];
#pragma unroll
        for (int j = 0; j < 8; j++) {
            sc[j][0] = sc[j][1] = sc[j][2] = sc[j][3] = 0.0f;
#pragma unroll
            for (int kk = 0; kk < 4; kk++) {
                unsigned b0 = __float_as_uint(Ks[j * 8 + gid][kk * 8 + tig]);
                unsigned b1 = __float_as_uint(Ks[j * 8 + gid][kk * 8 + tig + 4]);
                mma8(sc[j], aq[kk], b0, b1);
            }
        }

        // ---- P = keep * exp(S); row sums; stage tf32 P in smem ----
#pragma unroll
        for (int j = 0; j < 8; j++) {
            int col = j * 8 + 2 * tig;
            float kv0 = keeps[col];
            float kv1 = keeps[col + 1];
            float p00 = kv0 * __expf(fminf(sc[j][0], 60.0f));
            float p01 = kv1 * __expf(fminf(sc[j][1], 60.0f));
            float p10 = kv0 * __expf(fminf(sc[j][2], 60.0f));
            float p11 = kv1 * __expf(fminf(sc[j][3], 60.0f));
            lp0 += p00 + p01;
            lp1 += p10 + p11;
            *(float2*)&Ps[m0 + gid][col] = make_float2(tf32f(p00), tf32f(p01));
            *(float2*)&Ps[m0 + 8 + gid][col] = make_float2(tf32f(p10), tf32f(p11));
        }
        __syncwarp();  // Ps rows [m0,m0+16) are produced & consumed by this warp only

        // ---- O += P @ V : 8 k-steps x 4 n-tiles per warp ----
#pragma unroll
        for (int kk = 0; kk < 8; kk++) {
            unsigned ap[4];
            int kc = kk * 8;
            ap[0] = __float_as_uint(Ps[m0 + gid][kc + tig]);
            ap[1] = __float_as_uint(Ps[m0 + 8 + gid][kc + tig]);
            ap[2] = __float_as_uint(Ps[m0 + gid][kc + tig + 4]);
            ap[3] = __float_as_uint(Ps[m0 + 8 + gid][kc + tig + 4]);
#pragma unroll
            for (int j = 0; j < 4; j++) {
                unsigned b0 = __float_as_uint(Vs[kc + tig][j * 8 + gid]);
                unsigned b1 = __float_as_uint(Vs[kc + tig + 4][j * 8 + gid]);
                mma8(oc[j], ap, b0, b1);
            }
        }
        __syncthreads();
    }

    // Reduce row sums across the 4 lanes of each group (tig axis).
    lp0 += __shfl_xor_sync(0xffffffffu, lp0, 1);
    lp0 += __shfl_xor_sync(0xffffffffu, lp0, 2);
    lp1 += __shfl_xor_sync(0xffffffffu, lp1, 1);
    lp1 += __shfl_xor_sync(0xffffffffu, lp1, 2);
    float inv0 = 1.0f / fmaxf(lp0, 1e-30f);
    float inv1 = 1.0f / fmaxf(lp1, 1e-30f);

    int row0 = q0 + m0 + gid;
    int row1 = row0 + 8;
#pragma unroll
    for (int j = 0; j < 4; j++) {
        int col = head * HD + j * 8 + 2 * tig;
        *(float2*)&g_ao[row0 * C_DIM + col] = make_float2(oc[j][0] * inv0, oc[j][1] * inv0);
        *(float2*)&g_ao[row1 * C_DIM + col] = make_float2(oc[j][2] * inv1, oc[j][3] * inv1);
    }
}

// ---------------------------------------------------------------------------
// Kernel 4: proj GEMM + bias, zero non-kept queries, add residual.
// ---------------------------------------------------------------------------
__global__ void __launch_bounds__(256) proj_kernel(const float* __restrict__ x,
                                                   const float* __restrict__ w,
                                                   const float* __restrict__ b,
                                                   float* __restrict__ out) {
    __shared__ float As[64][33];
    __shared__ float Bs[64][33];
    int tid = threadIdx.x;
    int tx = tid & 15, ty = tid >> 4;
    int row0 = blockIdx.y * 64;
    int col0 = blockIdx.x * 64;
    float acc[4][4] = {};
    for (int k0 = 0; k0 < 256; k0 += 32) {
#pragma unroll
        for (int i = 0; i < 8; i++) {
            int e = tid + i * 256;
            int r = e >> 5, c = e & 31;
            As[r][c] = g_ao[(row0 + r) * 256 + k0 + c];
            Bs[r][c] = w[(col0 + r) * 256 + k0 + c];
        }
        __syncthreads();
#pragma unroll
        for (int kk = 0; kk < 32; kk++) {
            float a[4], bb[4];
#pragma unroll
            for (int i = 0; i < 4; i++) a[i] = As[ty * 4 + i][kk];
#pragma unroll
            for (int j = 0; j < 4; j++) bb[j] = Bs[tx * 4 + j][kk];
#pragma unroll
            for (int i = 0; i < 4; i++)
#pragma unroll
                for (int j = 0; j < 4; j++) acc[i][j] += a[i] * bb[j];
        }
        __syncthreads();
    }
#pragma unroll
    for (int i = 0; i < 4; i++) {
        int n = row0 + ty * 4 + i;
        float kp = g_keep[n];
#pragma unroll
        for (int j = 0; j < 4; j++) {
            int cc = col0 + tx * 4 + j;
            out[n * 256 + cc] = kp * (acc[i][j] + b[cc]) + x[n * 256 + cc];
        }
    }
}

extern "C" void kernel_launch(void* const* d_in, const int* in_sizes, int n_in,
                              void* d_out, int out_size) {
    const float* x      = (const float*)d_in[0];
    const float* dbz    = (const float*)d_in[1];
    const float* qkv_w  = (const float*)d_in[2];
    const float* proj_w = (const float*)d_in[3];
    const float* proj_b = (const float*)d_in[4];
    float* out = (float*)d_out;

    keep_kernel<<<16, 256>>>(dbz);
    qkv_kernel<<<dim3(12, 64), 256>>>(x, qkv_w);
    attn_kernel<<<dim3(64, 8), 128>>>();
    proj_kernel<<<dim3(4, 64), 256>>>(x, proj_w, proj_b, out);
}

// round 5
// speedup vs baseline: 4.8435x; 2.9642x over previous
#include <cuda_runtime.h>

#define N_TOK 4096
#define C_DIM 256
#define NH 8
#define HD 32
#define SCALE 0.17677669529663687f  // 1/sqrt(32)

// Scratch (device globals; no allocation allowed)
__device__ float g_keep[N_TOK];
// Q/K/V stored as packed bf16x2 words: [head][token][16 words of d-pairs]
__device__ unsigned g_q_bf[NH * N_TOK * (HD / 2)];
__device__ unsigned g_k_bf[NH * N_TOK * (HD / 2)];
__device__ unsigned g_v_bf[NH * N_TOK * (HD / 2)];
__device__ float g_ao[N_TOK * C_DIM];

// ---------------------------------------------------------------------------
// Helpers
// ---------------------------------------------------------------------------
__device__ __forceinline__ float tf32f(float f) {
    unsigned u;
    asm("cvt.rna.tf32.f32 %0, %1;" : "=r"(u) : "f"(f));
    return __uint_as_float(u);
}

// tf32 m16n8k8 (used by QKV / proj GEMMs)
__device__ __forceinline__ void mma8(float* c, const unsigned* a, unsigned b0, unsigned b1) {
    asm volatile(
        "mma.sync.aligned.m16n8k8.row.col.f32.tf32.tf32.f32 "
        "{%0,%1,%2,%3}, {%4,%5,%6,%7}, {%8,%9}, {%0,%1,%2,%3};"
        : "+f"(c[0]), "+f"(c[1]), "+f"(c[2]), "+f"(c[3])
        : "r"(a[0]), "r"(a[1]), "r"(a[2]), "r"(a[3]), "r"(b0), "r"(b1));
}

// bf16 m16n8k16 (attention)
__device__ __forceinline__ void mma16(float* c, const unsigned* a, unsigned b0, unsigned b1) {
    asm volatile(
        "mma.sync.aligned.m16n8k16.row.col.f32.bf16.bf16.f32 "
        "{%0,%1,%2,%3}, {%4,%5,%6,%7}, {%8,%9}, {%0,%1,%2,%3};"
        : "+f"(c[0]), "+f"(c[1]), "+f"(c[2]), "+f"(c[3])
        : "r"(a[0]), "r"(a[1]), "r"(a[2]), "r"(a[3]), "r"(b0), "r"(b1));
}

// pack (lo, hi) -> bf16x2 word
__device__ __forceinline__ unsigned packbf(float lo, float hi) {
    unsigned r;
    asm("cvt.rn.bf16x2.f32 %0, %1, %2;" : "=r"(r) : "f"(hi), "f"(lo));
    return r;
}

__device__ __forceinline__ void ldsm2t(unsigned& r0, unsigned& r1, const void* p) {
    unsigned addr = (unsigned)__cvta_generic_to_shared(p);
    asm volatile("ldmatrix.sync.aligned.m8n8.x2.trans.shared.b16 {%0,%1}, [%2];"
                 : "=r"(r0), "=r"(r1) : "r"(addr));
}

// ---------------------------------------------------------------------------
// Kernel 1: keep mask = 3x3 dilation of (dbz >= 15), per frame.
// ---------------------------------------------------------------------------
__global__ void keep_kernel(const float* __restrict__ dbz) {
    int idx = blockIdx.x * blockDim.x + threadIdx.x;
    if (idx >= N_TOK) return;
    int t = idx >> 10;
    int h = (idx >> 5) & 31;
    int w = idx & 31;
    const float* f = dbz + t * 1024;
    bool any = false;
#pragma unroll
    for (int dh = -1; dh <= 1; dh++) {
        int hh = h + dh;
        if (hh < 0 || hh >= 32) continue;
#pragma unroll
        for (int dw = -1; dw <= 1; dw++) {
            int ww = w + dw;
            if (ww < 0 || ww >= 32) continue;
            any = any || (f[hh * 32 + ww] >= 15.0f);
        }
    }
    g_keep[idx] = any ? 1.0f : 0.0f;
}

// ---------------------------------------------------------------------------
// Kernel 2: QKV GEMM with tf32 mma. C[4096,768] = X @ W^T.
// Block 128x64, 8 warps (4 row x 2 col), warp tile 32x32.
// Epilogue packs outputs to bf16x2 head-major Q(K,V); Q pre-scaled.
// ---------------------------------------------------------------------------
__global__ void __launch_bounds__(256) qkv_kernel(const float* __restrict__ x,
                                                  const float* __restrict__ w) {
    __shared__ float As[128][36];
    __shared__ float Bs[64][36];
    int tid = threadIdx.x;
    int lane = tid & 31;
    int warp = tid >> 5;
    int gid = lane >> 2, tig = lane & 3;
    int wr = warp >> 1, wc = warp & 1;
    int rows0 = blockIdx.y * 128;
    int cols0 = blockIdx.x * 64;

    float acc[2][4][4] = {};

    for (int k0 = 0; k0 < 256; k0 += 32) {
#pragma unroll
        for (int i = 0; i < 4; i++) {
            int idx = tid + i * 256;
            int r = idx >> 3, c4 = idx & 7;
            float4 v = *(const float4*)&x[(rows0 + r) * 256 + k0 + c4 * 4];
            As[r][c4 * 4 + 0] = tf32f(v.x);
            As[r][c4 * 4 + 1] = tf32f(v.y);
            As[r][c4 * 4 + 2] = tf32f(v.z);
            As[r][c4 * 4 + 3] = tf32f(v.w);
        }
#pragma unroll
        for (int i = 0; i < 2; i++) {
            int idx = tid + i * 256;
            int r = idx >> 3, c4 = idx & 7;
            float4 v = *(const float4*)&w[(cols0 + r) * 256 + k0 + c4 * 4];
            Bs[r][c4 * 4 + 0] = tf32f(v.x);
            Bs[r][c4 * 4 + 1] = tf32f(v.y);
            Bs[r][c4 * 4 + 2] = tf32f(v.z);
            Bs[r][c4 * 4 + 3] = tf32f(v.w);
        }
        __syncthreads();
#pragma unroll
        for (int kk = 0; kk < 4; kk++) {
            unsigned a[2][4];
#pragma unroll
            for (int mt = 0; mt < 2; mt++) {
                int rb = wr * 32 + mt * 16;
                a[mt][0] = __float_as_uint(As[rb + gid][kk * 8 + tig]);
                a[mt][1] = __float_as_uint(As[rb + 8 + gid][kk * 8 + tig]);
                a[mt][2] = __float_as_uint(As[rb + gid][kk * 8 + tig + 4]);
                a[mt][3] = __float_as_uint(As[rb + 8 + gid][kk * 8 + tig + 4]);
            }
#pragma unroll
            for (int nt = 0; nt < 4; nt++) {
                unsigned b0 = __float_as_uint(Bs[wc * 32 + nt * 8 + gid][kk * 8 + tig]);
                unsigned b1 = __float_as_uint(Bs[wc * 32 + nt * 8 + gid][kk * 8 + tig + 4]);
#pragma unroll
                for (int mt = 0; mt < 2; mt++) mma8(acc[mt][nt], a[mt], b0, b1);
            }
        }
        __syncthreads();
    }

#pragma unroll
    for (int mt = 0; mt < 2; mt++) {
        int r0 = rows0 + wr * 32 + mt * 16 + gid;
        int r1 = r0 + 8;
#pragma unroll
        for (int nt = 0; nt < 4; nt++) {
            int jj = cols0 + wc * 32 + nt * 8 + 2 * tig;
            int sel = jj >> 8;
            int head = (jj >> 5) & 7;
            int wd = (jj >> 1) & 15;
            unsigned* dst = (sel == 0) ? g_q_bf : (sel == 1) ? g_k_bf : g_v_bf;
            float m = (sel == 0) ? SCALE : 1.0f;
            dst[(head * N_TOK + r0) * 16 + wd] = packbf(acc[mt][nt][0] * m, acc[mt][nt][1] * m);
            dst[(head * N_TOK + r1) * 16 + wd] = packbf(acc[mt][nt][2] * m, acc[mt][nt][3] * m);
        }
    }
}

// ---------------------------------------------------------------------------
// Kernel 3: flash attention, bf16 m16n8k16. One (head, 128-query tile) per
// block, 256 threads = 8 warps; warp owns 16 q-rows. K/V tiles of 64 keys.
// No running max (logits ~N(0,0.33); clamp 60). V via ldmatrix.x2.trans.
// ---------------------------------------------------------------------------
__global__ void __launch_bounds__(256) attn_kernel() {
    __shared__ unsigned Qs[128][20];  // bf16x2 [q][d-pair], stride 20
    __shared__ unsigned Ks[64][20];   // bf16x2 [key][d-pair]
    __shared__ unsigned Vs[64][20];   // bf16x2 [key][d-pair] (ldmatrix source)
    __shared__ unsigned Ps[128][36];  // bf16x2 [q][key-pair], stride 36
    __shared__ float keeps[64];

    int tid = threadIdx.x;
    int lane = tid & 31;
    int warp = tid >> 5;
    int gid = lane >> 2, tig = lane & 3;
    int m0 = warp * 16;

    int head = blockIdx.y;
    int q0 = blockIdx.x * 128;
    const uint4* Qg = (const uint4*)g_q_bf + head * N_TOK * 4;
    const uint4* Kg = (const uint4*)g_k_bf + head * N_TOK * 4;
    const uint4* Vg = (const uint4*)g_v_bf + head * N_TOK * 4;

    // Load Q tile (pre-scaled bf16): 128 rows x 4 uint4.
#pragma unroll
    for (int i = 0; i < 2; i++) {
        int idx = tid + i * 256;
        int r = idx >> 2, c = idx & 3;
        *(uint4*)&Qs[r][c * 4] = Qg[(q0 + r) * 4 + c];
    }
    __syncthreads();

    // Q a-fragments, fixed for whole kernel (2 k-steps of 16).
    unsigned aq[2][4];
#pragma unroll
    for (int kk = 0; kk < 2; kk++) {
        aq[kk][0] = Qs[m0 + gid][kk * 8 + tig];
        aq[kk][1] = Qs[m0 + 8 + gid][kk * 8 + tig];
        aq[kk][2] = Qs[m0 + gid][kk * 8 + tig + 4];
        aq[kk][3] = Qs[m0 + 8 + gid][kk * 8 + tig + 4];
    }

    float oc[4][4] = {};          // O accum: 4 d-tiles of 8
    float lp0 = 0.0f, lp1 = 0.0f; // row sums (rows m0+gid, m0+8+gid)

    for (int k0 = 0; k0 < N_TOK; k0 += 64) {
        {
            int r = tid >> 2, c = tid & 3;
            *(uint4*)&Ks[r][c * 4] = Kg[(k0 + r) * 4 + c];
            *(uint4*)&Vs[r][c * 4] = Vg[(k0 + r) * 4 + c];
        }
        if (tid < 64) keeps[tid] = g_keep[k0 + tid];
        __syncthreads();

        // S = Q K^T, then P = keep * exp(S), staged as bf16x2.
#pragma unroll
        for (int j = 0; j < 8; j++) {
            float sc[4] = {};
#pragma unroll
            for (int kk = 0; kk < 2; kk++) {
                unsigned b0 = Ks[j * 8 + gid][kk * 8 + tig];
                unsigned b1 = Ks[j * 8 + gid][kk * 8 + tig + 4];
                mma16(sc, aq[kk], b0, b1);
            }
            int col = j * 8 + 2 * tig;
            float kv0 = keeps[col], kv1 = keeps[col + 1];
            float p00 = kv0 * __expf(fminf(sc[0], 60.0f));
            float p01 = kv1 * __expf(fminf(sc[1], 60.0f));
            float p10 = kv0 * __expf(fminf(sc[2], 60.0f));
            float p11 = kv1 * __expf(fminf(sc[3], 60.0f));
            lp0 += p00 + p01;
            lp1 += p10 + p11;
            Ps[m0 + gid][j * 4 + tig] = packbf(p00, p01);
            Ps[m0 + 8 + gid][j * 4 + tig] = packbf(p10, p11);
        }
        __syncwarp();  // Ps rows owned by this warp only

        // O += P V : 4 k-steps of 16 keys, 4 d-tiles.
#pragma unroll
        for (int kk = 0; kk < 4; kk++) {
            unsigned ap[4];
            ap[0] = Ps[m0 + gid][kk * 8 + tig];
            ap[1] = Ps[m0 + 8 + gid][kk * 8 + tig];
            ap[2] = Ps[m0 + gid][kk * 8 + tig + 4];
            ap[3] = Ps[m0 + 8 + gid][kk * 8 + tig + 4];
#pragma unroll
            for (int j = 0; j < 4; j++) {
                unsigned b0, b1;
                ldsm2t(b0, b1, &Vs[kk * 16 + (lane & 15)][j * 4]);
                mma16(oc[j], ap, b0, b1);
            }
        }
        __syncthreads();
    }

    // Reduce row sums over the 4 tig lanes, normalize, write fp32 ao.
    lp0 += __shfl_xor_sync(0xffffffffu, lp0, 1);
    lp0 += __shfl_xor_sync(0xffffffffu, lp0, 2);
    lp1 += __shfl_xor_sync(0xffffffffu, lp1, 1);
    lp1 += __shfl_xor_sync(0xffffffffu, lp1, 2);
    float inv0 = 1.0f / fmaxf(lp0, 1e-30f);
    float inv1 = 1.0f / fmaxf(lp1, 1e-30f);

    int row0 = q0 + m0 + gid;
    int row1 = row0 + 8;
#pragma unroll
    for (int j = 0; j < 4; j++) {
        int col = head * HD + j * 8 + 2 * tig;
        *(float2*)&g_ao[row0 * C_DIM + col] = make_float2(oc[j][0] * inv0, oc[j][1] * inv0);
        *(float2*)&g_ao[row1 * C_DIM + col] = make_float2(oc[j][2] * inv1, oc[j][3] * inv1);
    }
}

// ---------------------------------------------------------------------------
// Kernel 4: proj GEMM (tf32 mma) + bias, query-mask, residual.
// Block 128x64, 8 warps.
// ---------------------------------------------------------------------------
__global__ void __launch_bounds__(256) proj_kernel(const float* __restrict__ x,
                                                   const float* __restrict__ w,
                                                   const float* __restrict__ b,
                                                   float* __restrict__ out) {
    __shared__ float As[128][36];
    __shared__ float Bs[64][36];
    int tid = threadIdx.x;
    int lane = tid & 31;
    int warp = tid >> 5;
    int gid = lane >> 2, tig = lane & 3;
    int wr = warp >> 1, wc = warp & 1;
    int rows0 = blockIdx.y * 128;
    int cols0 = blockIdx.x * 64;

    float acc[2][4][4] = {};

    for (int k0 = 0; k0 < 256; k0 += 32) {
#pragma unroll
        for (int i = 0; i < 4; i++) {
            int idx = tid + i * 256;
            int r = idx >> 3, c4 = idx & 7;
            float4 v = *(const float4*)&g_ao[(rows0 + r) * 256 + k0 + c4 * 4];
            As[r][c4 * 4 + 0] = tf32f(v.x);
            As[r][c4 * 4 + 1] = tf32f(v.y);
            As[r][c4 * 4 + 2] = tf32f(v.z);
            As[r][c4 * 4 + 3] = tf32f(v.w);
        }
#pragma unroll
        for (int i = 0; i < 2; i++) {
            int idx = tid + i * 256;
            int r = idx >> 3, c4 = idx & 7;
            float4 v = *(const float4*)&w[(cols0 + r) * 256 + k0 + c4 * 4];
            Bs[r][c4 * 4 + 0] = tf32f(v.x);
            Bs[r][c4 * 4 + 1] = tf32f(v.y);
            Bs[r][c4 * 4 + 2] = tf32f(v.z);
            Bs[r][c4 * 4 + 3] = tf32f(v.w);
        }
        __syncthreads();
#pragma unroll
        for (int kk = 0; kk < 4; kk++) {
            unsigned a[2][4];
#pragma unroll
            for (int mt = 0; mt < 2; mt++) {
                int rb = wr * 32 + mt * 16;
                a[mt][0] = __float_as_uint(As[rb + gid][kk * 8 + tig]);
                a[mt][1] = __float_as_uint(As[rb + 8 + gid][kk * 8 + tig]);
                a[mt][2] = __float_as_uint(As[rb + gid][kk * 8 + tig + 4]);
                a[mt][3] = __float_as_uint(As[rb + 8 + gid][kk * 8 + tig + 4]);
            }
#pragma unroll
            for (int nt = 0; nt < 4; nt++) {
                unsigned b0 = __float_as_uint(Bs[wc * 32 + nt * 8 + gid][kk * 8 + tig]);
                unsigned b1 = __float_as_uint(Bs[wc * 32 + nt * 8 + gid][kk * 8 + tig + 4]);
#pragma unroll
                for (int mt = 0; mt < 2; mt++) mma8(acc[mt][nt], a[mt], b0, b1);
            }
        }
        __syncthreads();
    }

#pragma unroll
    for (int mt = 0; mt < 2; mt++) {
        int r0 = rows0 + wr * 32 + mt * 16 + gid;
        int r1 = r0 + 8;
        float kp0 = g_keep[r0], kp1 = g_keep[r1];
#pragma unroll
        for (int nt = 0; nt < 4; nt++) {
            int cc = cols0 + wc * 32 + nt * 8 + 2 * tig;
            float2 bb = *(const float2*)&b[cc];
            float2 x0 = *(const float2*)&x[r0 * 256 + cc];
            float2 x1 = *(const float2*)&x[r1 * 256 + cc];
            *(float2*)&out[r0 * 256 + cc] =
                make_float2(kp0 * (acc[mt][nt][0] + bb.x) + x0.x,
                            kp0 * (acc[mt][nt][1] + bb.y) + x0.y);
            *(float2*)&out[r1 * 256 + cc] =
                make_float2(kp1 * (acc[mt][nt][2] + bb.x) + x1.x,
                            kp1 * (acc[mt][nt][3] + bb.y) + x1.y);
        }
    }
}

extern "C" void kernel_launch(void* const* d_in, const int* in_sizes, int n_in,
                              void* d_out, int out_size) {
    const float* x      = (const float*)d_in[0];
    const float* dbz    = (const float*)d_in[1];
    const float* qkv_w  = (const float*)d_in[2];
    const float* proj_w = (const float*)d_in[3];
    const float* proj_b = (const float*)d_in[4];
    float* out = (float*)d_out;

    keep_kernel<<<16, 256>>>(dbz);
    qkv_kernel<<<dim3(12, 32), 256>>>(x, qkv_w);
    attn_kernel<<<dim3(32, 8), 256>>>();
    proj_kernel<<<dim3(4, 32), 256>>>(x, proj_w, proj_b, out);
}

// round 7
// speedup vs baseline: 6.8720x; 1.4188x over previous
#include <cuda_runtime.h>

#define N_TOK 4096
#define C_DIM 256
#define NH 8
#define HD 32
// SCALE * log2(e): softmax computed as exp2
#define SCALE_L2E 0.25510840297298685f
#define MASK_BIAS -100000.0f

// Scratch (device globals; no allocation allowed)
__device__ float g_keep[N_TOK];    // 0/1 for proj query masking
__device__ float g_kbias[N_TOK];   // 0 / -1e5 additive key mask
// Q/K/V stored as packed bf16x2 words: [head][token][16 words of d-pairs]
__device__ unsigned g_q_bf[NH * N_TOK * (HD / 2)];
__device__ unsigned g_k_bf[NH * N_TOK * (HD / 2)];
__device__ unsigned g_v_bf[NH * N_TOK * (HD / 2)];
__device__ float g_ao[N_TOK * C_DIM];

// ---------------------------------------------------------------------------
// Helpers
// ---------------------------------------------------------------------------
__device__ __forceinline__ void cp16(void* smem_dst, const void* gsrc) {
    unsigned a = (unsigned)__cvta_generic_to_shared(smem_dst);
    asm volatile("cp.async.cg.shared.global [%0], [%1], 16;" :: "r"(a), "l"(gsrc));
}
__device__ __forceinline__ void cp4(void* smem_dst, const void* gsrc) {
    unsigned a = (unsigned)__cvta_generic_to_shared(smem_dst);
    asm volatile("cp.async.ca.shared.global [%0], [%1], 4;" :: "r"(a), "l"(gsrc));
}
__device__ __forceinline__ void cp_commit() { asm volatile("cp.async.commit_group;"); }
__device__ __forceinline__ void cp_wait1() { asm volatile("cp.async.wait_group 1;"); }
__device__ __forceinline__ void cp_wait0() { asm volatile("cp.async.wait_group 0;"); }

__device__ __forceinline__ float ex2(float x) {
    float r;
    asm("ex2.approx.ftz.f32 %0, %1;" : "=f"(r) : "f"(x));
    return r;
}

// tf32 m16n8k8 (QKV / proj GEMMs; inputs truncated f32)
__device__ __forceinline__ void mma8(float* c, const unsigned* a, unsigned b0, unsigned b1) {
    asm volatile(
        "mma.sync.aligned.m16n8k8.row.col.f32.tf32.tf32.f32 "
        "{%0,%1,%2,%3}, {%4,%5,%6,%7}, {%8,%9}, {%0,%1,%2,%3};"
        : "+f"(c[0]), "+f"(c[1]), "+f"(c[2]), "+f"(c[3])
        : "r"(a[0]), "r"(a[1]), "r"(a[2]), "r"(a[3]), "r"(b0), "r"(b1));
}
// bf16 m16n8k16 (attention)
__device__ __forceinline__ void mma16(float* c, const unsigned* a, unsigned b0, unsigned b1) {
    asm volatile(
        "mma.sync.aligned.m16n8k16.row.col.f32.bf16.bf16.f32 "
        "{%0,%1,%2,%3}, {%4,%5,%6,%7}, {%8,%9}, {%0,%1,%2,%3};"
        : "+f"(c[0]), "+f"(c[1]), "+f"(c[2]), "+f"(c[3])
        : "r"(a[0]), "r"(a[1]), "r"(a[2]), "r"(a[3]), "r"(b0), "r"(b1));
}
__device__ __forceinline__ unsigned packbf(float lo, float hi) {
    unsigned r;
    asm("cvt.rn.bf16x2.f32 %0, %1, %2;" : "=r"(r) : "f"(hi), "f"(lo));
    return r;
}
__device__ __forceinline__ void ldsm2t(unsigned& r0, unsigned& r1, const void* p) {
    unsigned addr = (unsigned)__cvta_generic_to_shared(p);
    asm volatile("ldmatrix.sync.aligned.m8n8.x2.trans.shared.b16 {%0,%1}, [%2];"
                 : "=r"(r0), "=r"(r1) : "r"(addr));
}

// ---------------------------------------------------------------------------
// Kernel 1: keep mask = 3x3 dilation of (dbz >= 15); writes 0/1 and bias.
// ---------------------------------------------------------------------------
__global__ void keep_kernel(const float* __restrict__ dbz) {
    int idx = blockIdx.x * blockDim.x + threadIdx.x;
    if (idx >= N_TOK) return;
    int t = idx >> 10;
    int h = (idx >> 5) & 31;
    int w = idx & 31;
    const float* f = dbz + t * 1024;
    bool any = false;
#pragma unroll
    for (int dh = -1; dh <= 1; dh++) {
        int hh = h + dh;
        if (hh < 0 || hh >= 32) continue;
#pragma unroll
        for (int dw = -1; dw <= 1; dw++) {
            int ww = w + dw;
            if (ww < 0 || ww >= 32) continue;
            any = any || (f[hh * 32 + ww] >= 15.0f);
        }
    }
    g_keep[idx] = any ? 1.0f : 0.0f;
    g_kbias[idx] = any ? 0.0f : MASK_BIAS;
}

// ---------------------------------------------------------------------------
// Kernel 2: QKV GEMM, tf32 mma, 64x64 tile, 128 threads (4 warps of 16 rows),
// cp.async double-buffered over 8 k-chunks. Epilogue packs bf16x2 head-major.
// ---------------------------------------------------------------------------
__global__ void __launch_bounds__(128) qkv_kernel(const float* __restrict__ x,
                                                  const float* __restrict__ w) {
    __shared__ float As[2][64][36];
    __shared__ float Bs[2][64][36];
    int tid = threadIdx.x;
    int lane = tid & 31;
    int warp = tid >> 5;
    int gid = lane >> 2, tig = lane & 3;
    int m0 = warp * 16;
    int rows0 = blockIdx.y * 64;
    int cols0 = blockIdx.x * 64;

    float acc[8][4] = {};

    // prologue: chunk 0 -> buf 0
#pragma unroll
    for (int i = 0; i < 4; i++) {
        int idx = tid + i * 128;
        int r = idx >> 3, c4 = idx & 7;
        cp16(&As[0][r][c4 * 4], &x[(rows0 + r) * 256 + c4 * 4]);
        cp16(&Bs[0][r][c4 * 4], &w[(cols0 + r) * 256 + c4 * 4]);
    }
    cp_commit();

    for (int t = 0; t < 8; t++) {
        int b = t & 1;
        if (t < 7) {
            int k0 = (t + 1) * 32;
#pragma unroll
            for (int i = 0; i < 4; i++) {
                int idx = tid + i * 128;
                int r = idx >> 3, c4 = idx & 7;
                cp16(&As[b ^ 1][r][c4 * 4], &x[(rows0 + r) * 256 + k0 + c4 * 4]);
                cp16(&Bs[b ^ 1][r][c4 * 4], &w[(cols0 + r) * 256 + k0 + c4 * 4]);
            }
            cp_commit();
            cp_wait1();
        } else {
            cp_wait0();
        }
        __syncthreads();
#pragma unroll
        for (int kk = 0; kk < 4; kk++) {
            unsigned a[4];
            a[0] = __float_as_uint(As[b][m0 + gid][kk * 8 + tig]);
            a[1] = __float_as_uint(As[b][m0 + 8 + gid][kk * 8 + tig]);
            a[2] = __float_as_uint(As[b][m0 + gid][kk * 8 + tig + 4]);
            a[3] = __float_as_uint(As[b][m0 + 8 + gid][kk * 8 + tig + 4]);
#pragma unroll
            for (int nt = 0; nt < 8; nt++) {
                unsigned b0 = __float_as_uint(Bs[b][nt * 8 + gid][kk * 8 + tig]);
                unsigned b1 = __float_as_uint(Bs[b][nt * 8 + gid][kk * 8 + tig + 4]);
                mma8(acc[nt], a, b0, b1);
            }
        }
        __syncthreads();
    }

    int r0 = rows0 + m0 + gid;
    int r1 = r0 + 8;
#pragma unroll
    for (int nt = 0; nt < 8; nt++) {
        int jj = cols0 + nt * 8 + 2 * tig;
        int sel = jj >> 8;
        int head = (jj >> 5) & 7;
        int wd = (jj >> 1) & 15;
        unsigned* dst = (sel == 0) ? g_q_bf : (sel == 1) ? g_k_bf : g_v_bf;
        float m = (sel == 0) ? SCALE_L2E : 1.0f;
        dst[(head * N_TOK + r0) * 16 + wd] = packbf(acc[nt][0] * m, acc[nt][1] * m);
        dst[(head * N_TOK + r1) * 16 + wd] = packbf(acc[nt][2] * m, acc[nt][3] * m);
    }
}

// ---------------------------------------------------------------------------
// Kernel 3: flash attention, bf16 m16n8k16, register-resident P fragments.
// One (head, 128-q tile) per block, 256 threads; 64-key tiles, cp.async
// double-buffered. p = exp2(s + kbias); no running max, no clamp.
// ---------------------------------------------------------------------------
__global__ void __launch_bounds__(256) attn_kernel() {
    __shared__ unsigned Qs[128][20];
    __shared__ unsigned Ks[2][64][20];
    __shared__ unsigned Vs[2][64][20];
    __shared__ float kb[2][64];

    int tid = threadIdx.x;
    int lane = tid & 31;
    int warp = tid >> 5;
    int gid = lane >> 2, tig = lane & 3;
    int m0 = warp * 16;

    int head = blockIdx.y;
    int q0 = blockIdx.x * 128;
    const uint4* Qg = (const uint4*)g_q_bf + head * N_TOK * 4;
    const uint4* Kg = (const uint4*)g_k_bf + head * N_TOK * 4;
    const uint4* Vg = (const uint4*)g_v_bf + head * N_TOK * 4;

    // Load Q tile (pre-scaled by SCALE*log2e, bf16).
#pragma unroll
    for (int i = 0; i < 2; i++) {
        int idx = tid + i * 256;
        int r = idx >> 2, c = idx & 3;
        *(uint4*)&Qs[r][c * 4] = Qg[(q0 + r) * 4 + c];
    }

    // prologue: K/V tile 0 -> buf 0
    {
        int r = tid >> 2, c = tid & 3;
        cp16(&Ks[0][r][c * 4], &Kg[r * 4 + c]);
        cp16(&Vs[0][r][c * 4], &Vg[r * 4 + c]);
        if (tid < 64) cp4(&kb[0][tid], &g_kbias[tid]);
    }
    cp_commit();
    __syncthreads();

    unsigned aq[2][4];
#pragma unroll
    for (int kk = 0; kk < 2; kk++) {
        aq[kk][0] = Qs[m0 + gid][kk * 8 + tig];
        aq[kk][1] = Qs[m0 + 8 + gid][kk * 8 + tig];
        aq[kk][2] = Qs[m0 + gid][kk * 8 + tig + 4];
        aq[kk][3] = Qs[m0 + 8 + gid][kk * 8 + tig + 4];
    }

    float oc[4][4] = {};
    float lp0 = 0.0f, lp1 = 0.0f;

    for (int t = 0; t < 64; t++) {
        int b = t & 1;
        if (t < 63) {
            int k0 = (t + 1) * 64;
            int r = tid >> 2, c = tid & 3;
            cp16(&Ks[b ^ 1][r][c * 4], &Kg[(k0 + r) * 4 + c]);
            cp16(&Vs[b ^ 1][r][c * 4], &Vg[(k0 + r) * 4 + c]);
            if (tid < 64) cp4(&kb[b ^ 1][tid], &g_kbias[k0 + tid]);
            cp_commit();
            cp_wait1();
        } else {
            cp_wait0();
        }
        __syncthreads();

#pragma unroll
        for (int u = 0; u < 4; u++) {
            unsigned ap[4];
#pragma unroll
            for (int jj = 0; jj < 2; jj++) {
                int j = 2 * u + jj;
                float sc[4] = {};
#pragma unroll
                for (int kk = 0; kk < 2; kk++) {
                    unsigned b0 = Ks[b][j * 8 + gid][kk * 8 + tig];
                    unsigned b1 = Ks[b][j * 8 + gid][kk * 8 + tig + 4];
                    mma16(sc, aq[kk], b0, b1);
                }
                int col = j * 8 + 2 * tig;
                float kb0 = kb[b][col], kb1 = kb[b][col + 1];
                float p00 = ex2(sc[0] + kb0);
                float p01 = ex2(sc[1] + kb1);
                float p10 = ex2(sc[2] + kb0);
                float p11 = ex2(sc[3] + kb1);
                lp0 += p00 + p01;
                lp1 += p10 + p11;
                // C-fragment of S == A-fragment of PV: pack in registers.
                ap[jj * 2 + 0] = packbf(p00, p01);
                ap[jj * 2 + 1] = packbf(p10, p11);
            }
#pragma unroll
            for (int j2 = 0; j2 < 4; j2++) {
                unsigned b0, b1;
                ldsm2t(b0, b1, &Vs[b][u * 16 + (lane & 15)][j2 * 4]);
                mma16(oc[j2], ap, b0, b1);
            }
        }
        __syncthreads();
    }

    lp0 += __shfl_xor_sync(0xffffffffu, lp0, 1);
    lp0 += __shfl_xor_sync(0xffffffffu, lp0, 2);
    lp1 += __shfl_xor_sync(0xffffffffu, lp1, 1);
    lp1 += __shfl_xor_sync(0xffffffffu, lp1, 2);
    float inv0 = 1.0f / fmaxf(lp0, 1e-30f);
    float inv1 = 1.0f / fmaxf(lp1, 1e-30f);

    int row0 = q0 + m0 + gid;
    int row1 = row0 + 8;
#pragma unroll
    for (int j = 0; j < 4; j++) {
        int col = head * HD + j * 8 + 2 * tig;
        *(float2*)&g_ao[row0 * C_DIM + col] = make_float2(oc[j][0] * inv0, oc[j][1] * inv0);
        *(float2*)&g_ao[row1 * C_DIM + col] = make_float2(oc[j][2] * inv1, oc[j][3] * inv1);
    }
}

// ---------------------------------------------------------------------------
// Kernel 4: proj GEMM (tf32 mma) + bias, query-mask, residual.
// 64x64 tile, 128 threads, cp.async double-buffered.
// ---------------------------------------------------------------------------
__global__ void __launch_bounds__(128) proj_kernel(const float* __restrict__ x,
                                                   const float* __restrict__ w,
                                                   const float* __restrict__ bias,
                                                   float* __restrict__ out) {
    __shared__ float As[2][64][36];
    __shared__ float Bs[2][64][36];
    int tid = threadIdx.x;
    int lane = tid & 31;
    int warp = tid >> 5;
    int gid = lane >> 2, tig = lane & 3;
    int m0 = warp * 16;
    int rows0 = blockIdx.y * 64;
    int cols0 = blockIdx.x * 64;

    float acc[8][4] = {};

#pragma unroll
    for (int i = 0; i < 4; i++) {
        int idx = tid + i * 128;
        int r = idx >> 3, c4 = idx & 7;
        cp16(&As[0][r][c4 * 4], &g_ao[(rows0 + r) * 256 + c4 * 4]);
        cp16(&Bs[0][r][c4 * 4], &w[(cols0 + r) * 256 + c4 * 4]);
    }
    cp_commit();

    for (int t = 0; t < 8; t++) {
        int b = t & 1;
        if (t < 7) {
            int k0 = (t + 1) * 32;
#pragma unroll
            for (int i = 0; i < 4; i++) {
                int idx = tid + i * 128;
                int r = idx >> 3, c4 = idx & 7;
                cp16(&As[b ^ 1][r][c4 * 4], &g_ao[(rows0 + r) * 256 + k0 + c4 * 4]);
                cp16(&Bs[b ^ 1][r][c4 * 4], &w[(cols0 + r) * 256 + k0 + c4 * 4]);
            }
            cp_commit();
            cp_wait1();
        } else {
            cp_wait0();
        }
        __syncthreads();
#pragma unroll
        for (int kk = 0; kk < 4; kk++) {
            unsigned a[4];
            a[0] = __float_as_uint(As[b][m0 + gid][kk * 8 + tig]);
            a[1] = __float_as_uint(As[b][m0 + 8 + gid][kk * 8 + tig]);
            a[2] = __float_as_uint(As[b][m0 + gid][kk * 8 + tig + 4]);
            a[3] = __float_as_uint(As[b][m0 + 8 + gid][kk * 8 + tig + 4]);
#pragma unroll
            for (int nt = 0; nt < 8; nt++) {
                unsigned b0 = __float_as_uint(Bs[b][nt * 8 + gid][kk * 8 + tig]);
                unsigned b1 = __float_as_uint(Bs[b][nt * 8 + gid][kk * 8 + tig + 4]);
                mma8(acc[nt], a, b0, b1);
            }
        }
        __syncthreads();
    }

    int r0 = rows0 + m0 + gid;
    int r1 = r0 + 8;
    float kp0 = g_keep[r0], kp1 = g_keep[r1];
#pragma unroll
    for (int nt = 0; nt < 8; nt++) {
        int cc = cols0 + nt * 8 + 2 * tig;
        float2 bb = *(const float2*)&bias[cc];
        float2 x0 = *(const float2*)&x[r0 * 256 + cc];
        float2 x1 = *(const float2*)&x[r1 * 256 + cc];
        *(float2*)&out[r0 * 256 + cc] =
            make_float2(kp0 * (acc[nt][0] + bb.x) + x0.x,
                        kp0 * (acc[nt][1] + bb.y) + x0.y);
        *(float2*)&out[r1 * 256 + cc] =
            make_float2(kp1 * (acc[nt][2] + bb.x) + x1.x,
                        kp1 * (acc[nt][3] + bb.y) + x1.y);
    }
}

extern "C" void kernel_launch(void* const* d_in, const int* in_sizes, int n_in,
                              void* d_out, int out_size) {
    const float* x      = (const float*)d_in[0];
    const float* dbz    = (const float*)d_in[1];
    const float* qkv_w  = (const float*)d_in[2];
    const float* proj_w = (const float*)d_in[3];
    const float* proj_b = (const float*)d_in[4];
    float* out = (float*)d_out;

    keep_kernel<<<16, 256>>>(dbz);
    qkv_kernel<<<dim3(12, 64), 128>>>(x, qkv_w);
    attn_kernel<<<dim3(32, 8), 256>>>();
    proj_kernel<<<dim3(4, 64), 128>>>(x, proj_w, proj_b, out);
}

// round 12
// speedup vs baseline: 7.3194x; 1.0651x over previous
#include <cuda_runtime.h>

#define N_TOK 4096
#define C_DIM 256
#define NH 8
#define HD 32
// SCALE * log2(e): softmax computed as exp2
#define SCALE_L2E 0.25510840297298685f
#define MASK_BIAS -100000.0f

// Scratch (device globals; no allocation allowed)
__device__ float g_keep[N_TOK];    // 0/1 for proj query masking
__device__ float g_kbias[N_TOK];   // 0 / -1e5 additive key mask
// Q/K/V stored as packed bf16x2 words: [head][token][16 words of d-pairs]
__device__ unsigned g_q_bf[NH * N_TOK * (HD / 2)];
__device__ unsigned g_k_bf[NH * N_TOK * (HD / 2)];
__device__ unsigned g_v_bf[NH * N_TOK * (HD / 2)];
__device__ float g_ao[N_TOK * C_DIM];

// ---------------------------------------------------------------------------
// Helpers
// ---------------------------------------------------------------------------
__device__ __forceinline__ void cp16(void* smem_dst, const void* gsrc) {
    unsigned a = (unsigned)__cvta_generic_to_shared(smem_dst);
    asm volatile("cp.async.cg.shared.global [%0], [%1], 16;" :: "r"(a), "l"(gsrc));
}
__device__ __forceinline__ void cp4(void* smem_dst, const void* gsrc) {
    unsigned a = (unsigned)__cvta_generic_to_shared(smem_dst);
    asm volatile("cp.async.ca.shared.global [%0], [%1], 4;" :: "r"(a), "l"(gsrc));
}
__device__ __forceinline__ void cp_commit() { asm volatile("cp.async.commit_group;"); }
__device__ __forceinline__ void cp_wait1() { asm volatile("cp.async.wait_group 1;"); }
__device__ __forceinline__ void cp_wait0() { asm volatile("cp.async.wait_group 0;"); }

__device__ __forceinline__ float ex2(float x) {
    float r;
    asm("ex2.approx.ftz.f32 %0, %1;" : "=f"(r) : "f"(x));
    return r;
}

// tf32 m16n8k8 (QKV / proj GEMMs; inputs truncated f32)
__device__ __forceinline__ void mma8(float* c, const unsigned* a, unsigned b0, unsigned b1) {
    asm volatile(
        "mma.sync.aligned.m16n8k8.row.col.f32.tf32.tf32.f32 "
        "{%0,%1,%2,%3}, {%4,%5,%6,%7}, {%8,%9}, {%0,%1,%2,%3};"
        : "+f"(c[0]), "+f"(c[1]), "+f"(c[2]), "+f"(c[3])
        : "r"(a[0]), "r"(a[1]), "r"(a[2]), "r"(a[3]), "r"(b0), "r"(b1));
}
// bf16 m16n8k16 (attention)
__device__ __forceinline__ void mma16(float* c, const unsigned* a, unsigned b0, unsigned b1) {
    asm volatile(
        "mma.sync.aligned.m16n8k16.row.col.f32.bf16.bf16.f32 "
        "{%0,%1,%2,%3}, {%4,%5,%6,%7}, {%8,%9}, {%0,%1,%2,%3};"
        : "+f"(c[0]), "+f"(c[1]), "+f"(c[2]), "+f"(c[3])
        : "r"(a[0]), "r"(a[1]), "r"(a[2]), "r"(a[3]), "r"(b0), "r"(b1));
}
__device__ __forceinline__ unsigned packbf(float lo, float hi) {
    unsigned r;
    asm("cvt.rn.bf16x2.f32 %0, %1, %2;" : "=r"(r) : "f"(hi), "f"(lo));
    return r;
}
__device__ __forceinline__ void ldsm2t(unsigned& r0, unsigned& r1, const void* p) {
    unsigned addr = (unsigned)__cvta_generic_to_shared(p);
    asm volatile("ldmatrix.sync.aligned.m8n8.x2.trans.shared.b16 {%0,%1}, [%2];"
                 : "=r"(r0), "=r"(r1) : "r"(addr));
}

// ---------------------------------------------------------------------------
// Kernel 1: keep mask = 3x3 dilation of (dbz >= 15); writes 0/1 and bias.
// ---------------------------------------------------------------------------
__global__ void keep_kernel(const float* __restrict__ dbz) {
    int idx = blockIdx.x * blockDim.x + threadIdx.x;
    if (idx >= N_TOK) return;
    int t = idx >> 10;
    int h = (idx >> 5) & 31;
    int w = idx & 31;
    const float* f = dbz + t * 1024;
    bool any = false;
#pragma unroll
    for (int dh = -1; dh <= 1; dh++) {
        int hh = h + dh;
        if (hh < 0 || hh >= 32) continue;
#pragma unroll
        for (int dw = -1; dw <= 1; dw++) {
            int ww = w + dw;
            if (ww < 0 || ww >= 32) continue;
            any = any || (f[hh * 32 + ww] >= 15.0f);
        }
    }
    g_keep[idx] = any ? 1.0f : 0.0f;
    g_kbias[idx] = any ? 0.0f : MASK_BIAS;
}

// ---------------------------------------------------------------------------
// Kernel 2: QKV GEMM (R7-proven), tf32 mma, 64x64 tile, 128 threads,
// cp.async double-buffered over 8 k-chunks. Epilogue packs bf16x2 head-major.
// ---------------------------------------------------------------------------
__global__ void __launch_bounds__(128) qkv_kernel(const float* __restrict__ x,
                                                  const float* __restrict__ w) {
    __shared__ float As[2][64][36];
    __shared__ float Bs[2][64][36];
    int tid = threadIdx.x;
    int lane = tid & 31;
    int warp = tid >> 5;
    int gid = lane >> 2, tig = lane & 3;
    int m0 = warp * 16;
    int rows0 = blockIdx.y * 64;
    int cols0 = blockIdx.x * 64;

    float acc[8][4] = {};

#pragma unroll
    for (int i = 0; i < 4; i++) {
        int idx = tid + i * 128;
        int r = idx >> 3, c4 = idx & 7;
        cp16(&As[0][r][c4 * 4], &x[(rows0 + r) * 256 + c4 * 4]);
        cp16(&Bs[0][r][c4 * 4], &w[(cols0 + r) * 256 + c4 * 4]);
    }
    cp_commit();

    for (int t = 0; t < 8; t++) {
        int b = t & 1;
        if (t < 7) {
            int k0 = (t + 1) * 32;
#pragma unroll
            for (int i = 0; i < 4; i++) {
                int idx = tid + i * 128;
                int r = idx >> 3, c4 = idx & 7;
                cp16(&As[b ^ 1][r][c4 * 4], &x[(rows0 + r) * 256 + k0 + c4 * 4]);
                cp16(&Bs[b ^ 1][r][c4 * 4], &w[(cols0 + r) * 256 + k0 + c4 * 4]);
            }
            cp_commit();
            cp_wait1();
        } else {
            cp_wait0();
        }
        __syncthreads();
#pragma unroll
        for (int kk = 0; kk < 4; kk++) {
            unsigned a[4];
            a[0] = __float_as_uint(As[b][m0 + gid][kk * 8 + tig]);
            a[1] = __float_as_uint(As[b][m0 + 8 + gid][kk * 8 + tig]);
            a[2] = __float_as_uint(As[b][m0 + gid][kk * 8 + tig + 4]);
            a[3] = __float_as_uint(As[b][m0 + 8 + gid][kk * 8 + tig + 4]);
#pragma unroll
            for (int nt = 0; nt < 8; nt++) {
                unsigned b0 = __float_as_uint(Bs[b][nt * 8 + gid][kk * 8 + tig]);
                unsigned b1 = __float_as_uint(Bs[b][nt * 8 + gid][kk * 8 + tig + 4]);
                mma8(acc[nt], a, b0, b1);
            }
        }
        __syncthreads();
    }

    int r0 = rows0 + m0 + gid;
    int r1 = r0 + 8;
#pragma unroll
    for (int nt = 0; nt < 8; nt++) {
        int jj = cols0 + nt * 8 + 2 * tig;
        int sel = jj >> 8;
        int head = (jj >> 5) & 7;
        int wd = (jj >> 1) & 15;
        unsigned* dst = (sel == 0) ? g_q_bf : (sel == 1) ? g_k_bf : g_v_bf;
        float m = (sel == 0) ? SCALE_L2E : 1.0f;
        dst[(head * N_TOK + r0) * 16 + wd] = packbf(acc[nt][0] * m, acc[nt][1] * m);
        dst[(head * N_TOK + r1) * 16 + wd] = packbf(acc[nt][2] * m, acc[nt][3] * m);
    }
}

// ---------------------------------------------------------------------------
// Kernel 3: flash attention, bf16 m16n8k16. One (head, 256-q tile) per block,
// 256 threads = 8 warps x 32 q-rows (2 m-tiles of 16). 64 key-tiles of 64
// (full N_TOK=4096), cp.async double-buffered. K fragments via scalar LDS,
// each reused across both m-tiles. P register-resident.
// p = exp2(s + kbias); no running max, no clamp.
// ---------------------------------------------------------------------------
__global__ void __launch_bounds__(256) attn_kernel() {
    __shared__ unsigned Qs[256][20];
    __shared__ unsigned Ks[2][64][20];
    __shared__ unsigned Vs[2][64][20];
    __shared__ float kb[2][64];

    int tid = threadIdx.x;
    int lane = tid & 31;
    int warp = tid >> 5;
    int gid = lane >> 2, tig = lane & 3;
    int m0 = warp * 32;

    int head = blockIdx.y;
    int q0 = blockIdx.x * 256;
    const uint4* Qg = (const uint4*)g_q_bf + head * N_TOK * 4;
    const uint4* Kg = (const uint4*)g_k_bf + head * N_TOK * 4;
    const uint4* Vg = (const uint4*)g_v_bf + head * N_TOK * 4;

    // Load Q tile (pre-scaled by SCALE*log2e, bf16): 256 rows x 4 uint4.
#pragma unroll
    for (int i = 0; i < 4; i++) {
        int idx = tid + i * 256;
        int r = idx >> 2, c = idx & 3;
        *(uint4*)&Qs[r][c * 4] = Qg[(q0 + r) * 4 + c];
    }

    // prologue: K/V tile 0 -> buf 0
    {
        int r = tid >> 2, c = tid & 3;
        cp16(&Ks[0][r][c * 4], &Kg[r * 4 + c]);
        cp16(&Vs[0][r][c * 4], &Vg[r * 4 + c]);
        if (tid < 64) cp4(&kb[0][tid], &g_kbias[tid]);
    }
    cp_commit();
    __syncthreads();

    // Q a-fragments: 2 m-tiles x 2 k-steps, fixed for whole kernel.
    unsigned aq[2][2][4];
#pragma unroll
    for (int mt = 0; mt < 2; mt++)
#pragma unroll
        for (int kk = 0; kk < 2; kk++) {
            int rb = m0 + mt * 16;
            aq[mt][kk][0] = Qs[rb + gid][kk * 8 + tig];
            aq[mt][kk][1] = Qs[rb + 8 + gid][kk * 8 + tig];
            aq[mt][kk][2] = Qs[rb + gid][kk * 8 + tig + 4];
            aq[mt][kk][3] = Qs[rb + 8 + gid][kk * 8 + tig + 4];
        }

    float oc[2][4][4] = {};
    float lp[2][2] = {};

    // 64 key tiles x 64 keys = full 4096 keys (R8/R9 bug: looped only 16).
    for (int t = 0; t < 64; t++) {
        int b = t & 1;
        if (t < 63) {
            int k0 = (t + 1) * 64;
            int r = tid >> 2, c = tid & 3;
            cp16(&Ks[b ^ 1][r][c * 4], &Kg[(k0 + r) * 4 + c]);
            cp16(&Vs[b ^ 1][r][c * 4], &Vg[(k0 + r) * 4 + c]);
            if (tid < 64) cp4(&kb[b ^ 1][tid], &g_kbias[k0 + tid]);
            cp_commit();
            cp_wait1();
        } else {
            cp_wait0();
        }
        __syncthreads();

#pragma unroll
        for (int u = 0; u < 4; u++) {
            unsigned ap[2][4];
#pragma unroll
            for (int jj = 0; jj < 2; jj++) {
                int j = 2 * u + jj;
                // K fragment for this j-tile (scalar LDS, proven in R7);
                // reused for both m-tiles.
                unsigned kf0 = Ks[b][j * 8 + gid][tig];
                unsigned kf1 = Ks[b][j * 8 + gid][tig + 4];
                unsigned kf2 = Ks[b][j * 8 + gid][8 + tig];
                unsigned kf3 = Ks[b][j * 8 + gid][8 + tig + 4];
                int col = j * 8 + 2 * tig;
                float bi0 = kb[b][col], bi1 = kb[b][col + 1];
#pragma unroll
                for (int mt = 0; mt < 2; mt++) {
                    float sc[4] = {};
                    mma16(sc, aq[mt][0], kf0, kf1);
                    mma16(sc, aq[mt][1], kf2, kf3);
                    float p00 = ex2(sc[0] + bi0);
                    float p01 = ex2(sc[1] + bi1);
                    float p10 = ex2(sc[2] + bi0);
                    float p11 = ex2(sc[3] + bi1);
                    lp[mt][0] += p00 + p01;
                    lp[mt][1] += p10 + p11;
                    // C-fragment of S == A-fragment of PV: pack in registers.
                    ap[mt][jj * 2 + 0] = packbf(p00, p01);
                    ap[mt][jj * 2 + 1] = packbf(p10, p11);
                }
            }
#pragma unroll
            for (int j2 = 0; j2 < 4; j2++) {
                unsigned b0, b1;
                ldsm2t(b0, b1, &Vs[b][u * 16 + (lane & 15)][j2 * 4]);
                mma16(oc[0][j2], ap[0], b0, b1);
                mma16(oc[1][j2], ap[1], b0, b1);
            }
        }
        __syncthreads();
    }

#pragma unroll
    for (int mt = 0; mt < 2; mt++) {
        float lp0 = lp[mt][0], lp1 = lp[mt][1];
        lp0 += __shfl_xor_sync(0xffffffffu, lp0, 1);
        lp0 += __shfl_xor_sync(0xffffffffu, lp0, 2);
        lp1 += __shfl_xor_sync(0xffffffffu, lp1, 1);
        lp1 += __shfl_xor_sync(0xffffffffu, lp1, 2);
        float inv0 = 1.0f / fmaxf(lp0, 1e-30f);
        float inv1 = 1.0f / fmaxf(lp1, 1e-30f);

        int row0 = q0 + m0 + mt * 16 + gid;
        int row1 = row0 + 8;
#pragma unroll
        for (int j = 0; j < 4; j++) {
            int col = head * HD + j * 8 + 2 * tig;
            *(float2*)&g_ao[row0 * C_DIM + col] =
                make_float2(oc[mt][j][0] * inv0, oc[mt][j][1] * inv0);
            *(float2*)&g_ao[row1 * C_DIM + col] =
                make_float2(oc[mt][j][2] * inv1, oc[mt][j][3] * inv1);
        }
    }
}

// ---------------------------------------------------------------------------
// Kernel 4: proj GEMM (R7-proven, tf32 mma) + bias, query-mask, residual.
// 64x64 tile, 128 threads, cp.async double-buffered.
// ---------------------------------------------------------------------------
__global__ void __launch_bounds__(128) proj_kernel(const float* __restrict__ x,
                                                   const float* __restrict__ w,
                                                   const float* __restrict__ bias,
                                                   float* __restrict__ out) {
    __shared__ float As[2][64][36];
    __shared__ float Bs[2][64][36];
    int tid = threadIdx.x;
    int lane = tid & 31;
    int warp = tid >> 5;
    int gid = lane >> 2, tig = lane & 3;
    int m0 = warp * 16;
    int rows0 = blockIdx.y * 64;
    int cols0 = blockIdx.x * 64;

    float acc[8][4] = {};

#pragma unroll
    for (int i = 0; i < 4; i++) {
        int idx = tid + i * 128;
        int r = idx >> 3, c4 = idx & 7;
        cp16(&As[0][r][c4 * 4], &g_ao[(rows0 + r) * 256 + c4 * 4]);
        cp16(&Bs[0][r][c4 * 4], &w[(cols0 + r) * 256 + c4 * 4]);
    }
    cp_commit();

    for (int t = 0; t < 8; t++) {
        int b = t & 1;
        if (t < 7) {
            int k0 = (t + 1) * 32;
#pragma unroll
            for (int i = 0; i < 4; i++) {
                int idx = tid + i * 128;
                int r = idx >> 3, c4 = idx & 7;
                cp16(&As[b ^ 1][r][c4 * 4], &g_ao[(rows0 + r) * 256 + k0 + c4 * 4]);
                cp16(&Bs[b ^ 1][r][c4 * 4], &w[(cols0 + r) * 256 + k0 + c4 * 4]);
            }
            cp_commit();
            cp_wait1();
        } else {
            cp_wait0();
        }
        __syncthreads();
#pragma unroll
        for (int kk = 0; kk < 4; kk++) {
            unsigned a[4];
            a[0] = __float_as_uint(As[b][m0 + gid][kk * 8 + tig]);
            a[1] = __float_as_uint(As[b][m0 + 8 + gid][kk * 8 + tig]);
            a[2] = __float_as_uint(As[b][m0 + gid][kk * 8 + tig + 4]);
            a[3] = __float_as_uint(As[b][m0 + 8 + gid][kk * 8 + tig + 4]);
#pragma unroll
            for (int nt = 0; nt < 8; nt++) {
                unsigned b0 = __float_as_uint(Bs[b][nt * 8 + gid][kk * 8 + tig]);
                unsigned b1 = __float_as_uint(Bs[b][nt * 8 + gid][kk * 8 + tig + 4]);
                mma8(acc[nt], a, b0, b1);
            }
        }
        __syncthreads();
    }

    int r0 = rows0 + m0 + gid;
    int r1 = r0 + 8;
    float kp0 = g_keep[r0], kp1 = g_keep[r1];
#pragma unroll
    for (int nt = 0; nt < 8; nt++) {
        int cc = cols0 + nt * 8 + 2 * tig;
        float2 bb = *(const float2*)&bias[cc];
        float2 x0 = *(const float2*)&x[r0 * 256 + cc];
        float2 x1 = *(const float2*)&x[r1 * 256 + cc];
        *(float2*)&out[r0 * 256 + cc] =
            make_float2(kp0 * (acc[nt][0] + bb.x) + x0.x,
                        kp0 * (acc[nt][1] + bb.y) + x0.y);
        *(float2*)&out[r1 * 256 + cc] =
            make_float2(kp1 * (acc[nt][2] + bb.x) + x1.x,
                        kp1 * (acc[nt][3] + bb.y) + x1.y);
    }
}

extern "C" void kernel_launch(void* const* d_in, const int* in_sizes, int n_in,
                              void* d_out, int out_size) {
    const float* x      = (const float*)d_in[0];
    const float* dbz    = (const float*)d_in[1];
    const float* qkv_w  = (const float*)d_in[2];
    const float* proj_w = (const float*)d_in[3];
    const float* proj_b = (const float*)d_in[4];
    float* out = (float*)d_out;

    keep_kernel<<<16, 256>>>(dbz);
    qkv_kernel<<<dim3(12, 64), 128>>>(x, qkv_w);
    attn_kernel<<<dim3(16, 8), 256>>>();
    proj_kernel<<<dim3(4, 64), 128>>>(x, proj_w, proj_b, out);
}

// round 16
// speedup vs baseline: 7.5442x; 1.0307x over previous
#include <cuda_runtime.h>
#include <cuda_fp16.h>

#define N_TOK 4096
#define C_DIM 256
#define NH 8
#define HD 32
// SCALE * log2(e): softmax computed as exp2
#define SCALE_L2E 0.25510840297298685f

// Scratch (device globals; no allocation allowed)
__device__ float g_keep[N_TOK];     // 0/1 for proj query masking
__device__ __half g_kbh[N_TOK];     // 0 / -60000 additive key mask (fp16)
// Q/K/V stored as packed fp16x2 words: [head][token][16 words of d-pairs]
__device__ unsigned g_q_h[NH * N_TOK * (HD / 2)];
__device__ unsigned g_k_h[NH * N_TOK * (HD / 2)];
__device__ unsigned g_v_h[NH * N_TOK * (HD / 2)];
__device__ float g_ao[N_TOK * C_DIM];

// ---------------------------------------------------------------------------
// Helpers
// ---------------------------------------------------------------------------
__device__ __forceinline__ void cp16(void* smem_dst, const void* gsrc) {
    unsigned a = (unsigned)__cvta_generic_to_shared(smem_dst);
    asm volatile("cp.async.cg.shared.global [%0], [%1], 16;" :: "r"(a), "l"(gsrc));
}
__device__ __forceinline__ void cp4(void* smem_dst, const void* gsrc) {
    unsigned a = (unsigned)__cvta_generic_to_shared(smem_dst);
    asm volatile("cp.async.ca.shared.global [%0], [%1], 4;" :: "r"(a), "l"(gsrc));
}
__device__ __forceinline__ void cp_commit() { asm volatile("cp.async.commit_group;"); }
__device__ __forceinline__ void cp_wait1() { asm volatile("cp.async.wait_group 1;"); }
__device__ __forceinline__ void cp_wait0() { asm volatile("cp.async.wait_group 0;"); }

// tf32 m16n8k8 (QKV / proj GEMMs; inputs truncated f32)
__device__ __forceinline__ void mma8(float* c, const unsigned* a, unsigned b0, unsigned b1) {
    asm volatile(
        "mma.sync.aligned.m16n8k8.row.col.f32.tf32.tf32.f32 "
        "{%0,%1,%2,%3}, {%4,%5,%6,%7}, {%8,%9}, {%0,%1,%2,%3};"
        : "+f"(c[0]), "+f"(c[1]), "+f"(c[2]), "+f"(c[3])
        : "r"(a[0]), "r"(a[1]), "r"(a[2]), "r"(a[3]), "r"(b0), "r"(b1));
}
// fp16 m16n8k16 (attention)
__device__ __forceinline__ void mma16h(float* c, const unsigned* a, unsigned b0, unsigned b1) {
    asm volatile(
        "mma.sync.aligned.m16n8k16.row.col.f32.f16.f16.f32 "
        "{%0,%1,%2,%3}, {%4,%5,%6,%7}, {%8,%9}, {%0,%1,%2,%3};"
        : "+f"(c[0]), "+f"(c[1]), "+f"(c[2]), "+f"(c[3])
        : "r"(a[0]), "r"(a[1]), "r"(a[2]), "r"(a[3]), "r"(b0), "r"(b1));
}
// pack (lo, hi) f32 -> fp16x2 word
__device__ __forceinline__ unsigned packh(float lo, float hi) {
    unsigned r;
    asm("cvt.rn.f16x2.f32 %0, %1, %2;" : "=r"(r) : "f"(hi), "f"(lo));
    return r;
}
// p = exp2(s + bias), two lanes at once, result is fp16x2 A-fragment word
__device__ __forceinline__ unsigned p_pair(float s_lo, float s_hi, unsigned bias_h2) {
    unsigned r;
    asm("{\n\t"
        ".reg .b32 t;\n\t"
        "cvt.rn.f16x2.f32 t, %1, %2;\n\t"
        "add.rn.f16x2 t, t, %3;\n\t"
        "ex2.approx.f16x2 %0, t;\n\t"
        "}"
        : "=r"(r) : "f"(s_hi), "f"(s_lo), "r"(bias_h2));
    return r;
}
__device__ __forceinline__ void ldsm2t(unsigned& r0, unsigned& r1, const void* p) {
    unsigned addr = (unsigned)__cvta_generic_to_shared(p);
    asm volatile("ldmatrix.sync.aligned.m8n8.x2.trans.shared.b16 {%0,%1}, [%2];"
                 : "=r"(r0), "=r"(r1) : "r"(addr));
}

// ---------------------------------------------------------------------------
// Kernel 1: keep mask = 3x3 dilation of (dbz >= 15); 0/1 + fp16 key bias.
// ---------------------------------------------------------------------------
__global__ void keep_kernel(const float* __restrict__ dbz) {
    int idx = blockIdx.x * blockDim.x + threadIdx.x;
    if (idx >= N_TOK) return;
    int t = idx >> 10;
    int h = (idx >> 5) & 31;
    int w = idx & 31;
    const float* f = dbz + t * 1024;
    bool any = false;
#pragma unroll
    for (int dh = -1; dh <= 1; dh++) {
        int hh = h + dh;
        if (hh < 0 || hh >= 32) continue;
#pragma unroll
        for (int dw = -1; dw <= 1; dw++) {
            int ww = w + dw;
            if (ww < 0 || ww >= 32) continue;
            any = any || (f[hh * 32 + ww] >= 15.0f);
        }
    }
    g_keep[idx] = any ? 1.0f : 0.0f;
    g_kbh[idx] = __float2half(any ? 0.0f : -60000.0f);
}

// ---------------------------------------------------------------------------
// Kernel 2: QKV GEMM (R7-proven), tf32 mma, 64x64 tile, 128 threads,
// cp.async double-buffered. Epilogue packs fp16x2 head-major; Q pre-scaled.
// ---------------------------------------------------------------------------
__global__ void __launch_bounds__(128) qkv_kernel(const float* __restrict__ x,
                                                  const float* __restrict__ w) {
    __shared__ float As[2][64][36];
    __shared__ float Bs[2][64][36];
    int tid = threadIdx.x;
    int lane = tid & 31;
    int warp = tid >> 5;
    int gid = lane >> 2, tig = lane & 3;
    int m0 = warp * 16;
    int rows0 = blockIdx.y * 64;
    int cols0 = blockIdx.x * 64;

    float acc[8][4] = {};

#pragma unroll
    for (int i = 0; i < 4; i++) {
        int idx = tid + i * 128;
        int r = idx >> 3, c4 = idx & 7;
        cp16(&As[0][r][c4 * 4], &x[(rows0 + r) * 256 + c4 * 4]);
        cp16(&Bs[0][r][c4 * 4], &w[(cols0 + r) * 256 + c4 * 4]);
    }
    cp_commit();

    for (int t = 0; t < 8; t++) {
        int b = t & 1;
        if (t < 7) {
            int k0 = (t + 1) * 32;
#pragma unroll
            for (int i = 0; i < 4; i++) {
                int idx = tid + i * 128;
                int r = idx >> 3, c4 = idx & 7;
                cp16(&As[b ^ 1][r][c4 * 4], &x[(rows0 + r) * 256 + k0 + c4 * 4]);
                cp16(&Bs[b ^ 1][r][c4 * 4], &w[(cols0 + r) * 256 + k0 + c4 * 4]);
            }
            cp_commit();
            cp_wait1();
        } else {
            cp_wait0();
        }
        __syncthreads();
#pragma unroll
        for (int kk = 0; kk < 4; kk++) {
            unsigned a[4];
            a[0] = __float_as_uint(As[b][m0 + gid][kk * 8 + tig]);
            a[1] = __float_as_uint(As[b][m0 + 8 + gid][kk * 8 + tig]);
            a[2] = __float_as_uint(As[b][m0 + gid][kk * 8 + tig + 4]);
            a[3] = __float_as_uint(As[b][m0 + 8 + gid][kk * 8 + tig + 4]);
#pragma unroll
            for (int nt = 0; nt < 8; nt++) {
                unsigned b0 = __float_as_uint(Bs[b][nt * 8 + gid][kk * 8 + tig]);
                unsigned b1 = __float_as_uint(Bs[b][nt * 8 + gid][kk * 8 + tig + 4]);
                mma8(acc[nt], a, b0, b1);
            }
        }
        __syncthreads();
    }

    int r0 = rows0 + m0 + gid;
    int r1 = r0 + 8;
#pragma unroll
    for (int nt = 0; nt < 8; nt++) {
        int jj = cols0 + nt * 8 + 2 * tig;
        int sel = jj >> 8;
        int head = (jj >> 5) & 7;
        int wd = (jj >> 1) & 15;
        unsigned* dst = (sel == 0) ? g_q_h : (sel == 1) ? g_k_h : g_v_h;
        float m = (sel == 0) ? SCALE_L2E : 1.0f;
        dst[(head * N_TOK + r0) * 16 + wd] = packh(acc[nt][0] * m, acc[nt][1] * m);
        dst[(head * N_TOK + r1) * 16 + wd] = packh(acc[nt][2] * m, acc[nt][3] * m);
    }
}

// ---------------------------------------------------------------------------
// Kernel 3: flash attention, fp16 m16n8k16. One (head, 256-q tile) per block,
// 256 threads = 8 warps x 32 q-rows (2 m-tiles). 64 key-tiles of 64,
// cp.async double-buffered.
//   - P = ex2.approx.f16x2(s + bias): one MUFU op per 2 probs, result IS the
//     fp16 PV A-fragment (no pack, no scalar exp, no fp32 bias add).
//   - Row sums via ones-column appended to V (5th PV n-tile) -> fp32 in oc[4].
// ---------------------------------------------------------------------------
__global__ void __launch_bounds__(256) attn_kernel() {
    __shared__ unsigned Qs[256][20];
    __shared__ unsigned Ks[2][64][20];
    __shared__ unsigned Vs[2][64][28];  // words 0-15: V; 16-19: ones-column tile
    __shared__ unsigned kbh[2][32];     // fp16x2 key-bias pairs

    int tid = threadIdx.x;
    int lane = tid & 31;
    int warp = tid >> 5;
    int gid = lane >> 2, tig = lane & 3;
    int m0 = warp * 32;

    int head = blockIdx.y;
    int q0 = blockIdx.x * 256;
    const uint4* Qg = (const uint4*)g_q_h + head * N_TOK * 4;
    const uint4* Kg = (const uint4*)g_k_h + head * N_TOK * 4;
    const uint4* Vg = (const uint4*)g_v_h + head * N_TOK * 4;

    // Load Q tile (pre-scaled by SCALE*log2e, fp16): 256 rows x 4 uint4.
#pragma unroll
    for (int i = 0; i < 4; i++) {
        int idx = tid + i * 256;
        int r = idx >> 2, c = idx & 3;
        *(uint4*)&Qs[r][c * 4] = Qg[(q0 + r) * 4 + c];
    }

    // Ones-column tile of V (constant; cp.async never touches words 16-19):
    // col 32 = fp16 1.0 for every key row, cols 33-39 = 0.
    if (tid < 64) {
#pragma unroll
        for (int bb = 0; bb < 2; bb++) {
            Vs[bb][tid][16] = 0x00003C00u;
            Vs[bb][tid][17] = 0u;
            Vs[bb][tid][18] = 0u;
            Vs[bb][tid][19] = 0u;
        }
    }

    // prologue: K/V tile 0 -> buf 0
    {
        int r = tid >> 2, c = tid & 3;
        cp16(&Ks[0][r][c * 4], &Kg[r * 4 + c]);
        cp16(&Vs[0][r][c * 4], &Vg[r * 4 + c]);
        if (tid < 32) cp4(&kbh[0][tid], &g_kbh[2 * tid]);
    }
    cp_commit();
    __syncthreads();

    // Q a-fragments: 2 m-tiles x 2 k-steps, fixed for whole kernel.
    unsigned aq[2][2][4];
#pragma unroll
    for (int mt = 0; mt < 2; mt++)
#pragma unroll
        for (int kk = 0; kk < 2; kk++) {
            int rb = m0 + mt * 16;
            aq[mt][kk][0] = Qs[rb + gid][kk * 8 + tig];
            aq[mt][kk][1] = Qs[rb + 8 + gid][kk * 8 + tig];
            aq[mt][kk][2] = Qs[rb + gid][kk * 8 + tig + 4];
            aq[mt][kk][3] = Qs[rb + 8 + gid][kk * 8 + tig + 4];
        }

    float oc[2][5][4] = {};  // 4 d-tiles + 1 row-sum tile

    for (int t = 0; t < 64; t++) {
        int b = t & 1;
        if (t < 63) {
            int k0 = (t + 1) * 64;
            int r = tid >> 2, c = tid & 3;
            cp16(&Ks[b ^ 1][r][c * 4], &Kg[(k0 + r) * 4 + c]);
            cp16(&Vs[b ^ 1][r][c * 4], &Vg[(k0 + r) * 4 + c]);
            if (tid < 32) cp4(&kbh[b ^ 1][tid], &g_kbh[k0 + 2 * tid]);
            cp_commit();
            cp_wait1();
        } else {
            cp_wait0();
        }
        __syncthreads();

#pragma unroll
        for (int u = 0; u < 4; u++) {
            unsigned ap[2][4];
#pragma unroll
            for (int jj = 0; jj < 2; jj++) {
                int j = 2 * u + jj;
                // K fragment (scalar LDS, conflict-free), reused for both m-tiles.
                unsigned kf0 = Ks[b][j * 8 + gid][tig];
                unsigned kf1 = Ks[b][j * 8 + gid][tig + 4];
                unsigned kf2 = Ks[b][j * 8 + gid][8 + tig];
                unsigned kf3 = Ks[b][j * 8 + gid][8 + tig + 4];
                unsigned bias2 = kbh[b][j * 4 + tig];  // fp16 pair (col, col+1)
#pragma unroll
                for (int mt = 0; mt < 2; mt++) {
                    float sc[4] = {};
                    mma16h(sc, aq[mt][0], kf0, kf1);
                    mma16h(sc, aq[mt][1], kf2, kf3);
                    // P pair = exp2(s + bias) in one f16x2 MUFU; result is the
                    // PV A-fragment word directly.
                    ap[mt][jj * 2 + 0] = p_pair(sc[0], sc[1], bias2);
                    ap[mt][jj * 2 + 1] = p_pair(sc[2], sc[3], bias2);
                }
            }
#pragma unroll
            for (int j2 = 0; j2 < 5; j2++) {
                unsigned b0, b1;
                ldsm2t(b0, b1, &Vs[b][u * 16 + (lane & 15)][j2 * 4]);
                mma16h(oc[0][j2], ap[0], b0, b1);
                mma16h(oc[1][j2], ap[1], b0, b1);
            }
        }
        __syncthreads();
    }

#pragma unroll
    for (int mt = 0; mt < 2; mt++) {
        // Row sums live in the ones-column (col 32 => c0/c2 of tig==0 lanes).
        float lp0 = __shfl_sync(0xffffffffu, oc[mt][4][0], lane & 0x1C);
        float lp1 = __shfl_sync(0xffffffffu, oc[mt][4][2], lane & 0x1C);
        float inv0 = 1.0f / fmaxf(lp0, 1e-30f);
        float inv1 = 1.0f / fmaxf(lp1, 1e-30f);

        int row0 = q0 + m0 + mt * 16 + gid;
        int row1 = row0 + 8;
#pragma unroll
        for (int j = 0; j < 4; j++) {
            int col = head * HD + j * 8 + 2 * tig;
            *(float2*)&g_ao[row0 * C_DIM + col] =
                make_float2(oc[mt][j][0] * inv0, oc[mt][j][1] * inv0);
            *(float2*)&g_ao[row1 * C_DIM + col] =
                make_float2(oc[mt][j][2] * inv1, oc[mt][j][3] * inv1);
        }
    }
}

// ---------------------------------------------------------------------------
// Kernel 4: proj GEMM (R7-proven, tf32 mma) + bias, query-mask, residual.
// 64x64 tile, 128 threads, cp.async double-buffered.
// ---------------------------------------------------------------------------
__global__ void __launch_bounds__(128) proj_kernel(const float* __restrict__ x,
                                                   const float* __restrict__ w,
                                                   const float* __restrict__ bias,
                                                   float* __restrict__ out) {
    __shared__ float As[2][64][36];
    __shared__ float Bs[2][64][36];
    int tid = threadIdx.x;
    int lane = tid & 31;
    int warp = tid >> 5;
    int gid = lane >> 2, tig = lane & 3;
    int m0 = warp * 16;
    int rows0 = blockIdx.y * 64;
    int cols0 = blockIdx.x * 64;

    float acc[8][4] = {};

#pragma unroll
    for (int i = 0; i < 4; i++) {
        int idx = tid + i * 128;
        int r = idx >> 3, c4 = idx & 7;
        cp16(&As[0][r][c4 * 4], &g_ao[(rows0 + r) * 256 + c4 * 4]);
        cp16(&Bs[0][r][c4 * 4], &w[(cols0 + r) * 256 + c4 * 4]);
    }
    cp_commit();

    for (int t = 0; t < 8; t++) {
        int b = t & 1;
        if (t < 7) {
            int k0 = (t + 1) * 32;
#pragma unroll
            for (int i = 0; i < 4; i++) {
                int idx = tid + i * 128;
                int r = idx >> 3, c4 = idx & 7;
                cp16(&As[b ^ 1][r][c4 * 4], &g_ao[(rows0 + r) * 256 + k0 + c4 * 4]);
                cp16(&Bs[b ^ 1][r][c4 * 4], &w[(cols0 + r) * 256 + k0 + c4 * 4]);
            }
            cp_commit();
            cp_wait1();
        } else {
            cp_wait0();
        }
        __syncthreads();
#pragma unroll
        for (int kk = 0; kk < 4; kk++) {
            unsigned a[4];
            a[0] = __float_as_uint(As[b][m0 + gid][kk * 8 + tig]);
            a[1] = __float_as_uint(As[b][m0 + 8 + gid][kk * 8 + tig]);
            a[2] = __float_as_uint(As[b][m0 + gid][kk * 8 + tig + 4]);
            a[3] = __float_as_uint(As[b][m0 + 8 + gid][kk * 8 + tig + 4]);
#pragma unroll
            for (int nt = 0; nt < 8; nt++) {
                unsigned b0 = __float_as_uint(Bs[b][nt * 8 + gid][kk * 8 + tig]);
                unsigned b1 = __float_as_uint(Bs[b][nt * 8 + gid][kk * 8 + tig + 4]);
                mma8(acc[nt], a, b0, b1);
            }
        }
        __syncthreads();
    }

    int r0 = rows0 + m0 + gid;
    int r1 = r0 + 8;
    float kp0 = g_keep[r0], kp1 = g_keep[r1];
#pragma unroll
    for (int nt = 0; nt < 8; nt++) {
        int cc = cols0 + nt * 8 + 2 * tig;
        float2 bb = *(const float2*)&bias[cc];
        float2 x0 = *(const float2*)&x[r0 * 256 + cc];
        float2 x1 = *(const float2*)&x[r1 * 256 + cc];
        *(float2*)&out[r0 * 256 + cc] =
            make_float2(kp0 * (acc[nt][0] + bb.x) + x0.x,
                        kp0 * (acc[nt][1] + bb.y) + x0.y);
        *(float2*)&out[r1 * 256 + cc] =
            make_float2(kp1 * (acc[nt][2] + bb.x) + x1.x,
                        kp1 * (acc[nt][3] + bb.y) + x1.y);
    }
}

extern "C" void kernel_launch(void* const* d_in, const int* in_sizes, int n_in,
                              void* d_out, int out_size) {
    const float* x      = (const float*)d_in[0];
    const float* dbz    = (const float*)d_in[1];
    const float* qkv_w  = (const float*)d_in[2];
    const float* proj_w = (const float*)d_in[3];
    const float* proj_b = (const float*)d_in[4];
    float* out = (float*)d_out;

    keep_kernel<<<16, 256>>>(dbz);
    qkv_kernel<<<dim3(12, 64), 128>>>(x, qkv_w);
    attn_kernel<<<dim3(16, 8), 256>>>();
    proj_kernel<<<dim3(4, 64), 128>>>(x, proj_w, proj_b, out);
}

// round 17
// speedup vs baseline: 7.7860x; 1.0320x over previous
#include <cuda_runtime.h>
#include <cuda_fp16.h>

#define N_TOK 4096
#define C_DIM 256
#define NH 8
#define HD 32
// SCALE * log2(e): softmax computed as exp2
#define SCALE_L2E 0.25510840297298685f

// Scratch (device globals; no allocation allowed)
__device__ float g_keep[N_TOK];     // 0/1 for proj query masking
__device__ __half g_kbh[N_TOK];     // 0 / -60000 additive key mask (fp16)
// Q/K/V stored as packed fp16x2 words: [head][token][16 words of d-pairs]
__device__ unsigned g_q_h[NH * N_TOK * (HD / 2)];
__device__ unsigned g_k_h[NH * N_TOK * (HD / 2)];
__device__ unsigned g_v_h[NH * N_TOK * (HD / 2)];
// Split-K partials: unnormalized sum(p*V) and sum(p) per segment
__device__ float g_po[2][N_TOK][C_DIM];
__device__ float g_lps[2][NH][N_TOK];
__device__ float g_ao[N_TOK * C_DIM];

// ---------------------------------------------------------------------------
// Helpers
// ---------------------------------------------------------------------------
__device__ __forceinline__ void cp16(void* smem_dst, const void* gsrc) {
    unsigned a = (unsigned)__cvta_generic_to_shared(smem_dst);
    asm volatile("cp.async.cg.shared.global [%0], [%1], 16;" :: "r"(a), "l"(gsrc));
}
__device__ __forceinline__ void cp4(void* smem_dst, const void* gsrc) {
    unsigned a = (unsigned)__cvta_generic_to_shared(smem_dst);
    asm volatile("cp.async.ca.shared.global [%0], [%1], 4;" :: "r"(a), "l"(gsrc));
}
__device__ __forceinline__ void cp_commit() { asm volatile("cp.async.commit_group;"); }
__device__ __forceinline__ void cp_wait1() { asm volatile("cp.async.wait_group 1;"); }
__device__ __forceinline__ void cp_wait0() { asm volatile("cp.async.wait_group 0;"); }

// tf32 m16n8k8 (QKV / proj GEMMs; inputs truncated f32)
__device__ __forceinline__ void mma8(float* c, const unsigned* a, unsigned b0, unsigned b1) {
    asm volatile(
        "mma.sync.aligned.m16n8k8.row.col.f32.tf32.tf32.f32 "
        "{%0,%1,%2,%3}, {%4,%5,%6,%7}, {%8,%9}, {%0,%1,%2,%3};"
        : "+f"(c[0]), "+f"(c[1]), "+f"(c[2]), "+f"(c[3])
        : "r"(a[0]), "r"(a[1]), "r"(a[2]), "r"(a[3]), "r"(b0), "r"(b1));
}
// fp16 m16n8k16 (attention)
__device__ __forceinline__ void mma16h(float* c, const unsigned* a, unsigned b0, unsigned b1) {
    asm volatile(
        "mma.sync.aligned.m16n8k16.row.col.f32.f16.f16.f32 "
        "{%0,%1,%2,%3}, {%4,%5,%6,%7}, {%8,%9}, {%0,%1,%2,%3};"
        : "+f"(c[0]), "+f"(c[1]), "+f"(c[2]), "+f"(c[3])
        : "r"(a[0]), "r"(a[1]), "r"(a[2]), "r"(a[3]), "r"(b0), "r"(b1));
}
// pack (lo, hi) f32 -> fp16x2 word
__device__ __forceinline__ unsigned packh(float lo, float hi) {
    unsigned r;
    asm("cvt.rn.f16x2.f32 %0, %1, %2;" : "=r"(r) : "f"(hi), "f"(lo));
    return r;
}
// p = exp2(s + bias), two lanes at once, result is fp16x2 A-fragment word
__device__ __forceinline__ unsigned p_pair(float s_lo, float s_hi, unsigned bias_h2) {
    unsigned r;
    asm("{\n\t"
        ".reg .b32 t;\n\t"
        "cvt.rn.f16x2.f32 t, %1, %2;\n\t"
        "add.rn.f16x2 t, t, %3;\n\t"
        "ex2.approx.f16x2 %0, t;\n\t"
        "}"
        : "=r"(r) : "f"(s_hi), "f"(s_lo), "r"(bias_h2));
    return r;
}
__device__ __forceinline__ void ldsm2t(unsigned& r0, unsigned& r1, const void* p) {
    unsigned addr = (unsigned)__cvta_generic_to_shared(p);
    asm volatile("ldmatrix.sync.aligned.m8n8.x2.trans.shared.b16 {%0,%1}, [%2];"
                 : "=r"(r0), "=r"(r1) : "r"(addr));
}

// ---------------------------------------------------------------------------
// Kernel 1: keep mask = 3x3 dilation of (dbz >= 15); 0/1 + fp16 key bias.
// ---------------------------------------------------------------------------
__global__ void keep_kernel(const float* __restrict__ dbz) {
    int idx = blockIdx.x * blockDim.x + threadIdx.x;
    if (idx >= N_TOK) return;
    int t = idx >> 10;
    int h = (idx >> 5) & 31;
    int w = idx & 31;
    const float* f = dbz + t * 1024;
    bool any = false;
#pragma unroll
    for (int dh = -1; dh <= 1; dh++) {
        int hh = h + dh;
        if (hh < 0 || hh >= 32) continue;
#pragma unroll
        for (int dw = -1; dw <= 1; dw++) {
            int ww = w + dw;
            if (ww < 0 || ww >= 32) continue;
            any = any || (f[hh * 32 + ww] >= 15.0f);
        }
    }
    g_keep[idx] = any ? 1.0f : 0.0f;
    g_kbh[idx] = __float2half(any ? 0.0f : -60000.0f);
}

// ---------------------------------------------------------------------------
// Kernel 2: QKV GEMM (R7-proven), tf32 mma, 64x64 tile, 128 threads,
// cp.async double-buffered. Epilogue packs fp16x2 head-major; Q pre-scaled.
// ---------------------------------------------------------------------------
__global__ void __launch_bounds__(128) qkv_kernel(const float* __restrict__ x,
                                                  const float* __restrict__ w) {
    __shared__ float As[2][64][36];
    __shared__ float Bs[2][64][36];
    int tid = threadIdx.x;
    int lane = tid & 31;
    int warp = tid >> 5;
    int gid = lane >> 2, tig = lane & 3;
    int m0 = warp * 16;
    int rows0 = blockIdx.y * 64;
    int cols0 = blockIdx.x * 64;

    float acc[8][4] = {};

#pragma unroll
    for (int i = 0; i < 4; i++) {
        int idx = tid + i * 128;
        int r = idx >> 3, c4 = idx & 7;
        cp16(&As[0][r][c4 * 4], &x[(rows0 + r) * 256 + c4 * 4]);
        cp16(&Bs[0][r][c4 * 4], &w[(cols0 + r) * 256 + c4 * 4]);
    }
    cp_commit();

    for (int t = 0; t < 8; t++) {
        int b = t & 1;
        if (t < 7) {
            int k0 = (t + 1) * 32;
#pragma unroll
            for (int i = 0; i < 4; i++) {
                int idx = tid + i * 128;
                int r = idx >> 3, c4 = idx & 7;
                cp16(&As[b ^ 1][r][c4 * 4], &x[(rows0 + r) * 256 + k0 + c4 * 4]);
                cp16(&Bs[b ^ 1][r][c4 * 4], &w[(cols0 + r) * 256 + k0 + c4 * 4]);
            }
            cp_commit();
            cp_wait1();
        } else {
            cp_wait0();
        }
        __syncthreads();
#pragma unroll
        for (int kk = 0; kk < 4; kk++) {
            unsigned a[4];
            a[0] = __float_as_uint(As[b][m0 + gid][kk * 8 + tig]);
            a[1] = __float_as_uint(As[b][m0 + 8 + gid][kk * 8 + tig]);
            a[2] = __float_as_uint(As[b][m0 + gid][kk * 8 + tig + 4]);
            a[3] = __float_as_uint(As[b][m0 + 8 + gid][kk * 8 + tig + 4]);
#pragma unroll
            for (int nt = 0; nt < 8; nt++) {
                unsigned b0 = __float_as_uint(Bs[b][nt * 8 + gid][kk * 8 + tig]);
                unsigned b1 = __float_as_uint(Bs[b][nt * 8 + gid][kk * 8 + tig + 4]);
                mma8(acc[nt], a, b0, b1);
            }
        }
        __syncthreads();
    }

    int r0 = rows0 + m0 + gid;
    int r1 = r0 + 8;
#pragma unroll
    for (int nt = 0; nt < 8; nt++) {
        int jj = cols0 + nt * 8 + 2 * tig;
        int sel = jj >> 8;
        int head = (jj >> 5) & 7;
        int wd = (jj >> 1) & 15;
        unsigned* dst = (sel == 0) ? g_q_h : (sel == 1) ? g_k_h : g_v_h;
        float m = (sel == 0) ? SCALE_L2E : 1.0f;
        dst[(head * N_TOK + r0) * 16 + wd] = packh(acc[nt][0] * m, acc[nt][1] * m);
        dst[(head * N_TOK + r1) * 16 + wd] = packh(acc[nt][2] * m, acc[nt][3] * m);
    }
}

// ---------------------------------------------------------------------------
// Kernel 3: flash attention, fp16 m16n8k16, SPLIT-K over 2 key segments.
// Grid (16 q-tiles, 8 heads, 2 segs), 256 threads = 8 warps x 32 q-rows.
// Each block: 32 key-tiles of 64 (seg*2048 .. seg*2048+2047), cp.async
// double-buffered. Emits UNNORMALIZED sum(p*V) -> g_po[seg] and row sums
// (via ones-column, 5th PV n-tile) -> g_lps[seg]. No shuffles, no division.
// ---------------------------------------------------------------------------
__global__ void __launch_bounds__(256, 2) attn_kernel() {
    __shared__ unsigned Qs[256][20];
    __shared__ unsigned Ks[2][64][20];
    __shared__ unsigned Vs[2][64][28];  // words 0-15: V; 16-19: ones-column tile
    __shared__ unsigned kbh[2][32];     // fp16x2 key-bias pairs

    int tid = threadIdx.x;
    int lane = tid & 31;
    int warp = tid >> 5;
    int gid = lane >> 2, tig = lane & 3;
    int m0 = warp * 32;

    int head = blockIdx.y;
    int seg = blockIdx.z;
    int q0 = blockIdx.x * 256;
    int kbase = seg * 2048;
    const uint4* Qg = (const uint4*)g_q_h + head * N_TOK * 4;
    const uint4* Kg = (const uint4*)g_k_h + head * N_TOK * 4;
    const uint4* Vg = (const uint4*)g_v_h + head * N_TOK * 4;

    // Load Q tile (pre-scaled by SCALE*log2e, fp16): 256 rows x 4 uint4.
#pragma unroll
    for (int i = 0; i < 4; i++) {
        int idx = tid + i * 256;
        int r = idx >> 2, c = idx & 3;
        *(uint4*)&Qs[r][c * 4] = Qg[(q0 + r) * 4 + c];
    }

    // Ones-column tile of V (constant; cp.async never touches words 16-19).
    if (tid < 64) {
#pragma unroll
        for (int bb = 0; bb < 2; bb++) {
            Vs[bb][tid][16] = 0x00003C00u;
            Vs[bb][tid][17] = 0u;
            Vs[bb][tid][18] = 0u;
            Vs[bb][tid][19] = 0u;
        }
    }

    // prologue: K/V tile 0 of this segment -> buf 0
    {
        int r = tid >> 2, c = tid & 3;
        cp16(&Ks[0][r][c * 4], &Kg[(kbase + r) * 4 + c]);
        cp16(&Vs[0][r][c * 4], &Vg[(kbase + r) * 4 + c]);
        if (tid < 32) cp4(&kbh[0][tid], &g_kbh[kbase + 2 * tid]);
    }
    cp_commit();
    __syncthreads();

    // Q a-fragments: 2 m-tiles x 2 k-steps, fixed for whole kernel.
    unsigned aq[2][2][4];
#pragma unroll
    for (int mt = 0; mt < 2; mt++)
#pragma unroll
        for (int kk = 0; kk < 2; kk++) {
            int rb = m0 + mt * 16;
            aq[mt][kk][0] = Qs[rb + gid][kk * 8 + tig];
            aq[mt][kk][1] = Qs[rb + 8 + gid][kk * 8 + tig];
            aq[mt][kk][2] = Qs[rb + gid][kk * 8 + tig + 4];
            aq[mt][kk][3] = Qs[rb + 8 + gid][kk * 8 + tig + 4];
        }

    float oc[2][5][4] = {};  // 4 d-tiles + 1 row-sum tile

    // 32 key tiles x 64 keys = this segment's 2048 keys (2 segs = 4096 total).
    for (int t = 0; t < 32; t++) {
        int b = t & 1;
        if (t < 31) {
            int k0 = kbase + (t + 1) * 64;
            int r = tid >> 2, c = tid & 3;
            cp16(&Ks[b ^ 1][r][c * 4], &Kg[(k0 + r) * 4 + c]);
            cp16(&Vs[b ^ 1][r][c * 4], &Vg[(k0 + r) * 4 + c]);
            if (tid < 32) cp4(&kbh[b ^ 1][tid], &g_kbh[k0 + 2 * tid]);
            cp_commit();
            cp_wait1();
        } else {
            cp_wait0();
        }
        __syncthreads();

#pragma unroll
        for (int u = 0; u < 4; u++) {
            unsigned ap[2][4];
#pragma unroll
            for (int jj = 0; jj < 2; jj++) {
                int j = 2 * u + jj;
                // K fragment (scalar LDS, conflict-free), reused for both m-tiles.
                unsigned kf0 = Ks[b][j * 8 + gid][tig];
                unsigned kf1 = Ks[b][j * 8 + gid][tig + 4];
                unsigned kf2 = Ks[b][j * 8 + gid][8 + tig];
                unsigned kf3 = Ks[b][j * 8 + gid][8 + tig + 4];
                unsigned bias2 = kbh[b][j * 4 + tig];  // fp16 pair (col, col+1)
#pragma unroll
                for (int mt = 0; mt < 2; mt++) {
                    float sc[4] = {};
                    mma16h(sc, aq[mt][0], kf0, kf1);
                    mma16h(sc, aq[mt][1], kf2, kf3);
                    ap[mt][jj * 2 + 0] = p_pair(sc[0], sc[1], bias2);
                    ap[mt][jj * 2 + 1] = p_pair(sc[2], sc[3], bias2);
                }
            }
#pragma unroll
            for (int j2 = 0; j2 < 5; j2++) {
                unsigned b0, b1;
                ldsm2t(b0, b1, &Vs[b][u * 16 + (lane & 15)][j2 * 4]);
                mma16h(oc[0][j2], ap[0], b0, b1);
                mma16h(oc[1][j2], ap[1], b0, b1);
            }
        }
        __syncthreads();
    }

    // Epilogue: write unnormalized partials. Row sums sit in the ones-column
    // (col 32 = c0/c2 of the tig==0 lanes) — those lanes write g_lps directly.
#pragma unroll
    for (int mt = 0; mt < 2; mt++) {
        int row0 = q0 + m0 + mt * 16 + gid;
        int row1 = row0 + 8;
        if (tig == 0) {
            g_lps[seg][head][row0] = oc[mt][4][0];
            g_lps[seg][head][row1] = oc[mt][4][2];
        }
#pragma unroll
        for (int j = 0; j < 4; j++) {
            int col = head * HD + j * 8 + 2 * tig;
            *(float2*)&g_po[seg][row0][col] = make_float2(oc[mt][j][0], oc[mt][j][1]);
            *(float2*)&g_po[seg][row1][col] = make_float2(oc[mt][j][2], oc[mt][j][3]);
        }
    }
}

// ---------------------------------------------------------------------------
// Kernel 3b: merge split-K partials: ao = (po0+po1) / (lp0+lp1).
// ---------------------------------------------------------------------------
__global__ void merge_kernel() {
    int row = blockIdx.x;
    int col = threadIdx.x;
    int head = col >> 5;
    float lp = g_lps[0][head][row] + g_lps[1][head][row];
    float inv = 1.0f / fmaxf(lp, 1e-30f);
    g_ao[row * C_DIM + col] = (g_po[0][row][col] + g_po[1][row][col]) * inv;
}

// ---------------------------------------------------------------------------
// Kernel 4: proj GEMM (R7-proven, tf32 mma) + bias, query-mask, residual.
// 64x64 tile, 128 threads, cp.async double-buffered.
// ---------------------------------------------------------------------------
__global__ void __launch_bounds__(128) proj_kernel(const float* __restrict__ x,
                                                   const float* __restrict__ w,
                                                   const float* __restrict__ bias,
                                                   float* __restrict__ out) {
    __shared__ float As[2][64][36];
    __shared__ float Bs[2][64][36];
    int tid = threadIdx.x;
    int lane = tid & 31;
    int warp = tid >> 5;
    int gid = lane >> 2, tig = lane & 3;
    int m0 = warp * 16;
    int rows0 = blockIdx.y * 64;
    int cols0 = blockIdx.x * 64;

    float acc[8][4] = {};

#pragma unroll
    for (int i = 0; i < 4; i++) {
        int idx = tid + i * 128;
        int r = idx >> 3, c4 = idx & 7;
        cp16(&As[0][r][c4 * 4], &g_ao[(rows0 + r) * 256 + c4 * 4]);
        cp16(&Bs[0][r][c4 * 4], &w[(cols0 + r) * 256 + c4 * 4]);
    }
    cp_commit();

    for (int t = 0; t < 8; t++) {
        int b = t & 1;
        if (t < 7) {
            int k0 = (t + 1) * 32;
#pragma unroll
            for (int i = 0; i < 4; i++) {
                int idx = tid + i * 128;
                int r = idx >> 3, c4 = idx & 7;
                cp16(&As[b ^ 1][r][c4 * 4], &g_ao[(rows0 + r) * 256 + k0 + c4 * 4]);
                cp16(&Bs[b ^ 1][r][c4 * 4], &w[(cols0 + r) * 256 + k0 + c4 * 4]);
            }
            cp_commit();
            cp_wait1();
        } else {
            cp_wait0();
        }
        __syncthreads();
#pragma unroll
        for (int kk = 0; kk < 4; kk++) {
            unsigned a[4];
            a[0] = __float_as_uint(As[b][m0 + gid][kk * 8 + tig]);
            a[1] = __float_as_uint(As[b][m0 + 8 + gid][kk * 8 + tig]);
            a[2] = __float_as_uint(As[b][m0 + gid][kk * 8 + tig + 4]);
            a[3] = __float_as_uint(As[b][m0 + 8 + gid][kk * 8 + tig + 4]);
#pragma unroll
            for (int nt = 0; nt < 8; nt++) {
                unsigned b0 = __float_as_uint(Bs[b][nt * 8 + gid][kk * 8 + tig]);
                unsigned b1 = __float_as_uint(Bs[b][nt * 8 + gid][kk * 8 + tig + 4]);
                mma8(acc[nt], a, b0, b1);
            }
        }
        __syncthreads();
    }

    int r0 = rows0 + m0 + gid;
    int r1 = r0 + 8;
    float kp0 = g_keep[r0], kp1 = g_keep[r1];
#pragma unroll
    for (int nt = 0; nt < 8; nt++) {
        int cc = cols0 + nt * 8 + 2 * tig;
        float2 bb = *(const float2*)&bias[cc];
        float2 x0 = *(const float2*)&x[r0 * 256 + cc];
        float2 x1 = *(const float2*)&x[r1 * 256 + cc];
        *(float2*)&out[r0 * 256 + cc] =
            make_float2(kp0 * (acc[nt][0] + bb.x) + x0.x,
                        kp0 * (acc[nt][1] + bb.y) + x0.y);
        *(float2*)&out[r1 * 256 + cc] =
            make_float2(kp1 * (acc[nt][2] + bb.x) + x1.x,
                        kp1 * (acc[nt][3] + bb.y) + x1.y);
    }
}

extern "C" void kernel_launch(void* const* d_in, const int* in_sizes, int n_in,
                              void* d_out, int out_size) {
    const float* x      = (const float*)d_in[0];
    const float* dbz    = (const float*)d_in[1];
    const float* qkv_w  = (const float*)d_in[2];
    const float* proj_w = (const float*)d_in[3];
    const float* proj_b = (const float*)d_in[4];
    float* out = (float*)d_out;

    keep_kernel<<<16, 256>>>(dbz);
    qkv_kernel<<<dim3(12, 64), 128>>>(x, qkv_w);
    attn_kernel<<<dim3(16, 8, 2), 256>>>();
    merge_kernel<<<N_TOK, 256>>>();
    proj_kernel<<<dim3(4, 64), 128>>>(x, proj_w, proj_b, out);
}